// round 13
// baseline (speedup 1.0000x reference)
#include <cuda_runtime.h>
#include <cuda_fp16.h>
#include <math.h>
#include <stdint.h>

// Problem dims
#define B_  4
#define S_  2048
#define D_  1024
#define H_  16
#define DKH 64
#define DFF_ 4096
#define NT  (B_ * S_)   // 8192 tokens
#define QKVS 3072       // fused qkv row stride

typedef __half h16;

// ====================== PTX helpers (baseline ISA, sm_80+) ==================
__device__ __forceinline__ uint32_t smem_to_u32(const void* p) {
    uint32_t a;
    asm("{ .reg .u64 t; cvta.to.shared.u64 t, %1; cvt.u32.u64 %0, t; }" : "=r"(a) : "l"(p));
    return a;
}
__device__ __forceinline__ void cp16(uint32_t dst, const void* src) {
    asm volatile("cp.async.cg.shared.global [%0], [%1], 16;" :: "r"(dst), "l"(src));
}
#define CP_COMMIT() asm volatile("cp.async.commit_group;" ::: "memory")

__device__ __forceinline__ void ldm4(uint32_t* r, uint32_t addr) {
    asm volatile("ldmatrix.sync.aligned.m8n8.x4.shared.b16 {%0,%1,%2,%3}, [%4];"
        : "=r"(r[0]), "=r"(r[1]), "=r"(r[2]), "=r"(r[3]) : "r"(addr));
}
__device__ __forceinline__ void ldm4t(uint32_t* r, uint32_t addr) {
    asm volatile("ldmatrix.sync.aligned.m8n8.x4.trans.shared.b16 {%0,%1,%2,%3}, [%4];"
        : "=r"(r[0]), "=r"(r[1]), "=r"(r[2]), "=r"(r[3]) : "r"(addr));
}
__device__ __forceinline__ void mma_f16(float* d, const uint32_t* a,
                                        uint32_t b0, uint32_t b1) {
    asm volatile(
        "mma.sync.aligned.m16n8k16.row.col.f32.f16.f16.f32 "
        "{%0,%1,%2,%3}, {%4,%5,%6,%7}, {%8,%9}, {%0,%1,%2,%3};"
        : "+f"(d[0]), "+f"(d[1]), "+f"(d[2]), "+f"(d[3])
        : "r"(a[0]), "r"(a[1]), "r"(a[2]), "r"(a[3]), "r"(b0), "r"(b1));
}

__device__ __forceinline__ uint32_t pk2h(float a, float b) {
    return (uint32_t)__half_as_ushort(__float2half_rn(a)) |
           ((uint32_t)__half_as_ushort(__float2half_rn(b)) << 16);
}

// ---------------- scratch (device globals) ----------------------------------
__device__ __align__(256) float g_h1[(size_t)NT * D_];
__device__ __align__(256) h16 g_zh[(size_t)NT * D_];
__device__ __align__(256) h16 g_qkvh[(size_t)NT * QKVS];
__device__ __align__(256) h16 g_ah[(size_t)NT * D_];
__device__ __align__(256) h16 g_mh[(size_t)NT * DFF_];
__device__ __align__(256) h16 g_wc[(size_t)3*D_*D_];
__device__ __align__(256) h16 g_wo[(size_t)D_*D_];
__device__ __align__(256) h16 g_w1[(size_t)DFF_*D_];
__device__ __align__(256) h16 g_w2[(size_t)D_*DFF_];

// ---------------- single fused weight convert --------------------------------
__global__ __launch_bounds__(256) void convert_all(
    const float* __restrict__ wq, const float* __restrict__ wk,
    const float* __restrict__ wv, const float* __restrict__ wo,
    const float* __restrict__ w1, const float* __restrict__ w2,
    h16* __restrict__ wc, h16* __restrict__ dwo,
    h16* __restrict__ dw1, h16* __restrict__ dw2)
{
    int bx = blockIdx.x;
    const float* src; h16* dst; int i;
    if (bx < 1024)      { src = wq; dst = wc;                       i = bx * 256 + threadIdx.x; }
    else if (bx < 2048) { src = wk; dst = wc + (size_t)D_*D_;       i = (bx-1024) * 256 + threadIdx.x; }
    else if (bx < 3072) { src = wv; dst = wc + (size_t)2*D_*D_;     i = (bx-2048) * 256 + threadIdx.x; }
    else if (bx < 4096) { src = wo; dst = dwo;                      i = (bx-3072) * 256 + threadIdx.x; }
    else if (bx < 8192) { src = w1; dst = dw1;                      i = (bx-4096) * 256 + threadIdx.x; }
    else                { src = w2; dst = dw2;                      i = (bx-8192) * 256 + threadIdx.x; }
    float4 v = ((const float4*)src)[i];
    ((uint2*)dst)[i] = make_uint2(pk2h(v.x, v.y), pk2h(v.z, v.w));
}

// ---------------- LayerNorm (Bessel ddof=1, eps=1e-9) -> fp16 ---------------
__global__ __launch_bounds__(256) void layernorm_kernel(
    const float* __restrict__ x, const float* __restrict__ gamma,
    const float* __restrict__ beta, h16* __restrict__ yh)
{
    int row = blockIdx.x;
    int t = threadIdx.x;
    const float4* xr = (const float4*)(x + (size_t)row * D_);
    float4 v = xr[t];
    float s  = v.x + v.y + v.z + v.w;
    float ss = v.x*v.x + v.y*v.y + v.z*v.z + v.w*v.w;
    #pragma unroll
    for (int o = 16; o > 0; o >>= 1) {
        s  += __shfl_xor_sync(0xffffffffu, s,  o);
        ss += __shfl_xor_sync(0xffffffffu, ss, o);
    }
    __shared__ float shs[8], shq[8];
    int w = t >> 5, l = t & 31;
    if (l == 0) { shs[w] = s; shq[w] = ss; }
    __syncthreads();
    float S = 0.f, Q = 0.f;
    #pragma unroll
    for (int i = 0; i < 8; i++) { S += shs[i]; Q += shq[i]; }
    float mean = S * (1.f / (float)D_);
    float var  = (Q - (float)D_ * mean * mean) * (1.f / (float)(D_ - 1));
    float inv  = rsqrtf(var + 1e-9f);
    const float4 g  = ((const float4*)gamma)[t];
    const float4 be = ((const float4*)beta)[t];
    float o0 = g.x * (v.x - mean) * inv + be.x;
    float o1 = g.y * (v.y - mean) * inv + be.y;
    float o2 = g.z * (v.z - mean) * inv + be.z;
    float o3 = g.w * (v.w - mean) * inv + be.w;
    size_t idx = (size_t)row * (D_/4) + t;
    ((uint2*)yh)[idx] = make_uint2(pk2h(o0, o1), pk2h(o2, o3));
}

// ---------------- mma.sync fp16 single-term GEMM (best known: R12) ----------
#define MATB 16384   // 128 rows x 128 bytes
#define STB  (2 * MATB)
#define SMEM_GEMM (3 * STB)   // 98304

template<bool RELU, bool BIAS, bool RES, bool OUTF16>
__global__ __launch_bounds__(256, 2) void tc_gemm(
    const h16* __restrict__ Ah, const h16* __restrict__ Bh,
    const float* __restrict__ bias, const float* __restrict__ res,
    float* __restrict__ Cf, h16* __restrict__ Ch,
    int M, int N, int K)
{
    extern __shared__ char smem[];
    uint32_t sb = smem_to_u32(smem);
    int tid = threadIdx.x;
    int lane = tid & 31, wid = tid >> 5;
    int wm = wid & 1, wn = wid >> 1;
    int row0 = blockIdx.y * 128, col0 = blockIdx.x * 128;

    int lm = tid >> 1;
    int lc = tid & 1;
    const h16* aHs = Ah + (size_t)(row0 + lm) * K + lc * 32;
    const h16* bHs = Bh + (size_t)(col0 + lm) * K + lc * 32;
    uint32_t dRow = (uint32_t)(lm << 7);
    uint32_t dCol[4];
    #pragma unroll
    for (int j = 0; j < 4; j++)
        dCol[j] = (uint32_t)(((lc * 64 + j * 16) ^ ((lm & 7) << 4)));

    auto load_stage = [&](int p, int kt) {
        uint32_t s0 = sb + p * STB + dRow;
        size_t ko = (size_t)kt * 64;
        #pragma unroll
        for (int j = 0; j < 4; j++) cp16(s0 + dCol[j], aHs + ko + j * 8);
        #pragma unroll
        for (int j = 0; j < 4; j++) cp16(s0 + MATB + dCol[j], bHs + ko + j * 8);
    };

    int g = lane >> 3, r = lane & 7;
    uint32_t aRow[4], bRow[2];
    #pragma unroll
    for (int mt = 0; mt < 4; mt++)
        aRow[mt] = (uint32_t)((wm * 64 + mt * 16 + (g & 1) * 8 + r) << 7);
    #pragma unroll
    for (int nb = 0; nb < 2; nb++)
        bRow[nb] = (uint32_t)((wn * 32 + nb * 16 + (g >> 1) * 8 + r) << 7);
    uint32_t aColSw[4], bColSw[4];
    #pragma unroll
    for (int h = 0; h < 4; h++) {
        aColSw[h] = (uint32_t)(((h << 5) + ((g >> 1) << 4)) ^ (r << 4));
        bColSw[h] = (uint32_t)(((h << 5) + ((g & 1) << 4)) ^ (r << 4));
    }

    float acc[4][4][4];
    #pragma unroll
    for (int i = 0; i < 4; i++)
        #pragma unroll
        for (int j = 0; j < 4; j++)
            #pragma unroll
            for (int e = 0; e < 4; e++) acc[i][j][e] = 0.f;

    int KT = K / 64;
    load_stage(0, 0); CP_COMMIT();
    load_stage(1, 1); CP_COMMIT();

    uint32_t fa[2][4][4], fb[2][2][4];
    int s = 0;
    for (int kt = 0; kt < KT; kt++) {
        __syncthreads();
        if (kt + 2 < KT) {
            int sw = s + 2; if (sw >= 3) sw -= 3;
            load_stage(sw, kt + 2);
        }
        CP_COMMIT();
        asm volatile("cp.async.wait_group 2;" ::: "memory");
        uint32_t st = sb + s * STB;

        #pragma unroll
        for (int mt = 0; mt < 4; mt++)
            ldm4(fa[0][mt], st + aRow[mt] + aColSw[0]);
        #pragma unroll
        for (int nb = 0; nb < 2; nb++)
            ldm4(fb[0][nb], st + MATB + bRow[nb] + bColSw[0]);

        #pragma unroll
        for (int h = 0; h < 4; h++) {
            int cur = h & 1, nxt = cur ^ 1;
            if (h < 3) {
                #pragma unroll
                for (int mt = 0; mt < 4; mt++)
                    ldm4(fa[nxt][mt], st + aRow[mt] + aColSw[h + 1]);
                #pragma unroll
                for (int nb = 0; nb < 2; nb++)
                    ldm4(fb[nxt][nb], st + MATB + bRow[nb] + bColSw[h + 1]);
            }
            #pragma unroll
            for (int mt = 0; mt < 4; mt++)
                #pragma unroll
                for (int nt = 0; nt < 4; nt++)
                    mma_f16(acc[mt][nt], fa[cur][mt],
                            fb[cur][nt >> 1][(nt & 1) * 2],
                            fb[cur][nt >> 1][(nt & 1) * 2 + 1]);
        }
        if (++s >= 3) s = 0;
    }

    // epilogue
    #pragma unroll
    for (int mt = 0; mt < 4; mt++) {
        int r_lo = row0 + wm * 64 + mt * 16 + (lane >> 2);
        #pragma unroll
        for (int nt = 0; nt < 4; nt++) {
            int col = col0 + wn * 32 + nt * 8 + (lane & 3) * 2;
            float* d = acc[mt][nt];
            float bi0 = 0.f, bi1 = 0.f;
            if (BIAS) { bi0 = __ldg(bias + col); bi1 = __ldg(bias + col + 1); }
            #pragma unroll
            for (int half = 0; half < 2; half++) {
                int row = r_lo + half * 8;
                float v0 = d[half * 2 + 0], v1 = d[half * 2 + 1];
                if (BIAS) { v0 += bi0; v1 += bi1; }
                if (RELU) { v0 = fmaxf(v0, 0.f); v1 = fmaxf(v1, 0.f); }
                size_t base = (size_t)row * N + col;
                if (RES) {
                    float2 rr = *(const float2*)(res + base);
                    v0 += rr.x; v1 += rr.y;
                }
                if (OUTF16) {
                    *(uint32_t*)(Ch + base) = pk2h(v0, v1);
                } else {
                    *(float2*)(Cf + base) = make_float2(v0, v1);
                }
            }
        }
    }
}

// ---------------- Tensor-core flash attention --------------------------------
// CTA: 128 q-rows x one head. 8 warps x 16 rows. 128-key chunks, double buffer,
// 2 CTAs/SM. Q persistent in dedicated smem region (re-ldmatrix'd per chunk);
// softmax in log2 domain (exp2f).
#define AROWB 144
#define AQ_BYTES (128 * AROWB)      // 18432
#define A_V   18432                 // within stage: K[0,18432), V[18432,36864)
#define A_M   36864                 // mask: 128 ints = 512B
#define A_STRIDE 37376
#define A_SMEM (AQ_BYTES + 2 * A_STRIDE)   // 93184

__global__ __launch_bounds__(256, 2) void attention_tc(
    const h16* __restrict__ qkvh, const int* __restrict__ mask,
    h16* __restrict__ oh)
{
    extern __shared__ char smem[];
    uint32_t sb = smem_to_u32(smem);
    uint32_t stb = sb + AQ_BYTES;             // stages base
    int tid = threadIdx.x, lane = tid & 31, w = tid >> 5;
    int bh_ = blockIdx.y, b = bh_ >> 4, h = bh_ & 15;
    int q0 = blockIdx.x * 128;
    size_t hoff = (size_t)h * DKH;
    int g = lane >> 3, r = lane & 7;

    // ---- stage Q (persistent region) ----
    {
        int lm = tid >> 1;
        int lc = (tid & 1) * 4;
        size_t go = (size_t)(b * S_ + q0 + lm) * QKVS + hoff + lc * 8;
        uint32_t d0 = sb + (uint32_t)(lm * AROWB + lc * 16);
        #pragma unroll
        for (int j = 0; j < 4; j++)
            cp16(d0 + j * 16, qkvh + go + j * 8);
        CP_COMMIT();
    }

    const h16* kbh = qkvh + (size_t)b * S_ * QKVS + D_ + hoff;
    const h16* vb  = qkvh + (size_t)b * S_ * QKVS + 2 * D_ + hoff;
    const int* mrow = mask + (size_t)b * S_;

    // chunk = 128 keys: K rows 128 x 128B, V rows 128 x 128B, mask 128 ints
    auto load_chunk = [&](int stg_i, int c) {
        uint32_t stg = stb + stg_i * A_STRIDE;
        int lm = tid >> 1;
        int lc = tid & 1;          // half-row: 32 h16 = 64B = 4 x 16B
        size_t go = (size_t)(c * 128 + lm) * QKVS + lc * 32;
        uint32_t d = stg + (uint32_t)(lm * AROWB + lc * 64);
        #pragma unroll
        for (int j = 0; j < 4; j++) cp16(d + j * 16,       kbh + go + j * 8);
        #pragma unroll
        for (int j = 0; j < 4; j++) cp16(d + A_V + j * 16, vb + go + j * 8);
        if (tid < 128)
            asm volatile("cp.async.ca.shared.global [%0], [%1], 4;"
                :: "r"(stg + A_M + tid * 4), "l"(mrow + c * 128 + tid));
    };

    const int NC = S_ / 128;   // 16
    load_chunk(0, 0); CP_COMMIT();
    load_chunk(1, 1); CP_COMMIT();

    uint32_t qBase = sb + (uint32_t)((w * 16 + (g & 1) * 8 + r) * AROWB + (g >> 1) * 16);
    uint32_t bKoff = (uint32_t)(((g >> 1) * 8 + r) * AROWB + (g & 1) * 16);
    uint32_t vOff  = (uint32_t)(((g & 1) * 8 + r) * AROWB + (g >> 1) * 16);

    float m0 = -1e30f, m1 = -1e30f, l0 = 0.f, l1 = 0.f;
    float acc[8][4];
    #pragma unroll
    for (int i = 0; i < 8; i++)
        #pragma unroll
        for (int e = 0; e < 4; e++) acc[i][e] = 0.f;

    const float SCL = 0.125f * 1.4426950408889634f;   // 1/sqrt(64) * log2(e)

    for (int c = 0; c < NC; c++) {
        if (c + 1 < NC) { asm volatile("cp.async.wait_group 1;" ::: "memory"); }
        else            { asm volatile("cp.async.wait_group 0;" ::: "memory"); }
        __syncthreads();
        uint32_t stg = stb + (c & 1) * A_STRIDE;

        float s[16][4];
        #pragma unroll
        for (int i = 0; i < 16; i++)
            #pragma unroll
            for (int e = 0; e < 4; e++) s[i][e] = 0.f;

        // S = Q K^T (128 keys)
        #pragma unroll
        for (int ks = 0; ks < 4; ks++) {
            uint32_t qf[4];
            ldm4(qf, qBase + ks * 32);
            #pragma unroll
            for (int nb = 0; nb < 8; nb++) {
                uint32_t bh4[4];
                ldm4(bh4, stg + bKoff + nb * (16 * AROWB) + ks * 32);
                mma_f16(s[nb*2],   qf, bh4[0], bh4[1]);
                mma_f16(s[nb*2+1], qf, bh4[2], bh4[3]);
            }
        }

        // scale (log2 domain) + mask
        const int* ms = (const int*)(smem + AQ_BYTES + (size_t)(c & 1) * A_STRIDE + A_M);
        #pragma unroll
        for (int nt = 0; nt < 16; nt++) {
            int cc = nt * 8 + (lane & 3) * 2;
            int mv0 = ms[cc], mv1 = ms[cc + 1];
            #pragma unroll
            for (int e = 0; e < 4; e++) s[nt][e] *= SCL;
            if (mv0 == 0) { s[nt][0] = -1e9f; s[nt][2] = -1e9f; }
            if (mv1 == 0) { s[nt][1] = -1e9f; s[nt][3] = -1e9f; }
        }

        // online softmax (base 2), rows r and r+8 per thread
        float mx0 = -1e30f, mx1 = -1e30f;
        #pragma unroll
        for (int nt = 0; nt < 16; nt++) {
            mx0 = fmaxf(mx0, fmaxf(s[nt][0], s[nt][1]));
            mx1 = fmaxf(mx1, fmaxf(s[nt][2], s[nt][3]));
        }
        mx0 = fmaxf(mx0, __shfl_xor_sync(0xffffffffu, mx0, 1));
        mx0 = fmaxf(mx0, __shfl_xor_sync(0xffffffffu, mx0, 2));
        mx1 = fmaxf(mx1, __shfl_xor_sync(0xffffffffu, mx1, 1));
        mx1 = fmaxf(mx1, __shfl_xor_sync(0xffffffffu, mx1, 2));
        float mn0 = fmaxf(m0, mx0), mn1 = fmaxf(m1, mx1);
        float sc0 = exp2f(m0 - mn0), sc1 = exp2f(m1 - mn1);
        m0 = mn0; m1 = mn1;
        float rs0 = 0.f, rs1 = 0.f;
        #pragma unroll
        for (int nt = 0; nt < 16; nt++) {
            s[nt][0] = exp2f(s[nt][0] - mn0); rs0 += s[nt][0];
            s[nt][1] = exp2f(s[nt][1] - mn0); rs0 += s[nt][1];
            s[nt][2] = exp2f(s[nt][2] - mn1); rs1 += s[nt][2];
            s[nt][3] = exp2f(s[nt][3] - mn1); rs1 += s[nt][3];
        }
        rs0 += __shfl_xor_sync(0xffffffffu, rs0, 1);
        rs0 += __shfl_xor_sync(0xffffffffu, rs0, 2);
        rs1 += __shfl_xor_sync(0xffffffffu, rs1, 1);
        rs1 += __shfl_xor_sync(0xffffffffu, rs1, 2);
        l0 = l0 * sc0 + rs0;
        l1 = l1 * sc1 + rs1;
        #pragma unroll
        for (int no = 0; no < 8; no++) {
            acc[no][0] *= sc0; acc[no][1] *= sc0;
            acc[no][2] *= sc1; acc[no][3] *= sc1;
        }

        // O += P V   (8 k16 groups across the 128-key chunk)
        #pragma unroll
        for (int kb = 0; kb < 8; kb++) {
            uint32_t a4[4];
            a4[0] = pk2h(s[kb*2][0],   s[kb*2][1]);
            a4[1] = pk2h(s[kb*2][2],   s[kb*2][3]);
            a4[2] = pk2h(s[kb*2+1][0], s[kb*2+1][1]);
            a4[3] = pk2h(s[kb*2+1][2], s[kb*2+1][3]);
            #pragma unroll
            for (int db = 0; db < 4; db++) {
                uint32_t bv[4];
                ldm4t(bv, stg + A_V + vOff + kb * (16 * AROWB) + db * 32);
                mma_f16(acc[db*2],   a4, bv[0], bv[1]);
                mma_f16(acc[db*2+1], a4, bv[2], bv[3]);
            }
        }

        __syncthreads();
        if (c + 2 < NC) { load_chunk(c & 1, c + 2); CP_COMMIT(); }
    }

    // ---- output: O / l -> fp16 ----
    float inv0 = 1.f / l0, inv1 = 1.f / l1;
    int row0 = q0 + w * 16 + (lane >> 2);
    size_t t0 = (size_t)(b * S_ + row0) * D_ + hoff;
    size_t t1 = t0 + (size_t)8 * D_;
    #pragma unroll
    for (int no = 0; no < 8; no++) {
        int cc = no * 8 + (lane & 3) * 2;
        *(uint32_t*)(oh + t0 + cc) = pk2h(acc[no][0] * inv0, acc[no][1] * inv0);
        *(uint32_t*)(oh + t1 + cc) = pk2h(acc[no][2] * inv1, acc[no][3] * inv1);
    }
}

// ---------------- launch ----------------------------------------------------
extern "C" void kernel_launch(void* const* d_in, const int* in_sizes, int n_in,
                              void* d_out, int out_size)
{
    (void)in_sizes; (void)n_in; (void)out_size;
    const float* x    = (const float*)d_in[0];
    const int*   mask = (const int*)  d_in[1];
    const float* wq   = (const float*)d_in[2];
    const float* wk   = (const float*)d_in[3];
    const float* wv   = (const float*)d_in[4];
    const float* wo   = (const float*)d_in[5];
    const float* w1   = (const float*)d_in[6];
    const float* b1   = (const float*)d_in[7];
    const float* w2   = (const float*)d_in[8];
    const float* b2   = (const float*)d_in[9];
    const float* g1   = (const float*)d_in[10];
    const float* be1  = (const float*)d_in[11];
    const float* g2   = (const float*)d_in[12];
    const float* be2  = (const float*)d_in[13];
    float* out = (float*)d_out;

    float *h1;
    h16 *zh, *qkvh, *ah, *mh;
    h16 *wc, *wop, *w1p, *w2p;
    cudaGetSymbolAddress((void**)&h1, g_h1);
    cudaGetSymbolAddress((void**)&zh, g_zh);
    cudaGetSymbolAddress((void**)&qkvh, g_qkvh);
    cudaGetSymbolAddress((void**)&ah, g_ah);
    cudaGetSymbolAddress((void**)&mh, g_mh);
    cudaGetSymbolAddress((void**)&wc, g_wc);
    cudaGetSymbolAddress((void**)&wop, g_wo);
    cudaGetSymbolAddress((void**)&w1p, g_w1);
    cudaGetSymbolAddress((void**)&w2p, g_w2);

    cudaFuncSetAttribute(tc_gemm<false,false,false,true >, cudaFuncAttributeMaxDynamicSharedMemorySize, SMEM_GEMM);
    cudaFuncSetAttribute(tc_gemm<false,false,true ,false>, cudaFuncAttributeMaxDynamicSharedMemorySize, SMEM_GEMM);
    cudaFuncSetAttribute(tc_gemm<true ,true ,false,true >, cudaFuncAttributeMaxDynamicSharedMemorySize, SMEM_GEMM);
    cudaFuncSetAttribute(tc_gemm<false,true ,true ,false>, cudaFuncAttributeMaxDynamicSharedMemorySize, SMEM_GEMM);
    cudaFuncSetAttribute(attention_tc, cudaFuncAttributeMaxDynamicSharedMemorySize, A_SMEM);

    // 1: fused weight conversions (single launch)
    convert_all<<<12288, 256>>>(wq, wk, wv, wo, w1, w2, wc, wop, w1p, w2p);

    // 2: LN1 -> fp16
    layernorm_kernel<<<NT, 256>>>(x, g1, be1, zh);

    // 3: fused QKV GEMM (N = 3072) -> fp16
    dim3 gQKV(QKVS / 128, NT / 128);
    tc_gemm<false,false,false,true><<<gQKV, 256, SMEM_GEMM>>>(
        zh, wc, nullptr, nullptr, nullptr, qkvh, NT, QKVS, D_);

    // 4: attention (tensor core) -> fp16
    dim3 gAtt(S_ / 128, B_ * H_);
    attention_tc<<<gAtt, 256, A_SMEM>>>(qkvh, mask, ah);

    // 5: h1 = x + attn @ wo^T
    dim3 gP(D_ / 128, NT / 128);
    tc_gemm<false,false,true,false><<<gP, 256, SMEM_GEMM>>>(
        ah, wop, nullptr, x, h1, nullptr, NT, D_, D_);

    // 6: LN2 -> fp16
    layernorm_kernel<<<NT, 256>>>(h1, g2, be2, zh);

    // 7: FFN1: mid = relu(z @ w1^T + b1) -> fp16
    dim3 gF1(DFF_ / 128, NT / 128);
    tc_gemm<true,true,false,true><<<gF1, 256, SMEM_GEMM>>>(
        zh, w1p, b1, nullptr, nullptr, mh, NT, DFF_, D_);

    // 8: FFN2: out = h1 + mid @ w2^T + b2
    dim3 gF2(D_ / 128, NT / 128);
    tc_gemm<false,true,true,false><<<gF2, 256, SMEM_GEMM>>>(
        mh, w2p, b2, h1, out, nullptr, NT, D_, DFF_);
}

// round 15
// speedup vs baseline: 1.0535x; 1.0535x over previous
#include <cuda_runtime.h>
#include <cuda_fp16.h>
#include <math.h>
#include <stdint.h>

// Problem dims
#define B_  4
#define S_  2048
#define D_  1024
#define H_  16
#define DKH 64
#define DFF_ 4096
#define NT  (B_ * S_)   // 8192 tokens
#define QKVS 3072       // fused qkv row stride

typedef __half h16;

// ====================== PTX helpers (baseline ISA, sm_80+) ==================
__device__ __forceinline__ uint32_t smem_to_u32(const void* p) {
    uint32_t a;
    asm("{ .reg .u64 t; cvta.to.shared.u64 t, %1; cvt.u32.u64 %0, t; }" : "=r"(a) : "l"(p));
    return a;
}
__device__ __forceinline__ void cp16(uint32_t dst, const void* src) {
    asm volatile("cp.async.cg.shared.global [%0], [%1], 16;" :: "r"(dst), "l"(src));
}
#define CP_COMMIT() asm volatile("cp.async.commit_group;" ::: "memory")

__device__ __forceinline__ void ldm4(uint32_t* r, uint32_t addr) {
    asm volatile("ldmatrix.sync.aligned.m8n8.x4.shared.b16 {%0,%1,%2,%3}, [%4];"
        : "=r"(r[0]), "=r"(r[1]), "=r"(r[2]), "=r"(r[3]) : "r"(addr));
}
__device__ __forceinline__ void ldm4t(uint32_t* r, uint32_t addr) {
    asm volatile("ldmatrix.sync.aligned.m8n8.x4.trans.shared.b16 {%0,%1,%2,%3}, [%4];"
        : "=r"(r[0]), "=r"(r[1]), "=r"(r[2]), "=r"(r[3]) : "r"(addr));
}
__device__ __forceinline__ void mma_f16(float* d, const uint32_t* a,
                                        uint32_t b0, uint32_t b1) {
    asm volatile(
        "mma.sync.aligned.m16n8k16.row.col.f32.f16.f16.f32 "
        "{%0,%1,%2,%3}, {%4,%5,%6,%7}, {%8,%9}, {%0,%1,%2,%3};"
        : "+f"(d[0]), "+f"(d[1]), "+f"(d[2]), "+f"(d[3])
        : "r"(a[0]), "r"(a[1]), "r"(a[2]), "r"(a[3]), "r"(b0), "r"(b1));
}

__device__ __forceinline__ uint32_t pk2h(float a, float b) {
    return (uint32_t)__half_as_ushort(__float2half_rn(a)) |
           ((uint32_t)__half_as_ushort(__float2half_rn(b)) << 16);
}

// ---------------- scratch (device globals) ----------------------------------
__device__ __align__(256) float g_h1[(size_t)NT * D_];
__device__ __align__(256) h16 g_zh[(size_t)NT * D_];
__device__ __align__(256) h16 g_qkvh[(size_t)NT * QKVS];
__device__ __align__(256) h16 g_ah[(size_t)NT * D_];
__device__ __align__(256) h16 g_mh[(size_t)NT * DFF_];
__device__ __align__(256) h16 g_wc[(size_t)3*D_*D_];
__device__ __align__(256) h16 g_wo[(size_t)D_*D_];
__device__ __align__(256) h16 g_w1[(size_t)DFF_*D_];
__device__ __align__(256) h16 g_w2[(size_t)D_*DFF_];

// ---------------- single fused weight convert --------------------------------
__global__ __launch_bounds__(256) void convert_all(
    const float* __restrict__ wq, const float* __restrict__ wk,
    const float* __restrict__ wv, const float* __restrict__ wo,
    const float* __restrict__ w1, const float* __restrict__ w2,
    h16* __restrict__ wc, h16* __restrict__ dwo,
    h16* __restrict__ dw1, h16* __restrict__ dw2)
{
    int bx = blockIdx.x;
    const float* src; h16* dst; int i;
    if (bx < 1024)      { src = wq; dst = wc;                       i = bx * 256 + threadIdx.x; }
    else if (bx < 2048) { src = wk; dst = wc + (size_t)D_*D_;       i = (bx-1024) * 256 + threadIdx.x; }
    else if (bx < 3072) { src = wv; dst = wc + (size_t)2*D_*D_;     i = (bx-2048) * 256 + threadIdx.x; }
    else if (bx < 4096) { src = wo; dst = dwo;                      i = (bx-3072) * 256 + threadIdx.x; }
    else if (bx < 8192) { src = w1; dst = dw1;                      i = (bx-4096) * 256 + threadIdx.x; }
    else                { src = w2; dst = dw2;                      i = (bx-8192) * 256 + threadIdx.x; }
    float4 v = ((const float4*)src)[i];
    ((uint2*)dst)[i] = make_uint2(pk2h(v.x, v.y), pk2h(v.z, v.w));
}

// ---------------- LayerNorm (Bessel ddof=1, eps=1e-9) -> fp16 ---------------
__global__ __launch_bounds__(256) void layernorm_kernel(
    const float* __restrict__ x, const float* __restrict__ gamma,
    const float* __restrict__ beta, h16* __restrict__ yh)
{
    int row = blockIdx.x;
    int t = threadIdx.x;
    const float4* xr = (const float4*)(x + (size_t)row * D_);
    float4 v = xr[t];
    float s  = v.x + v.y + v.z + v.w;
    float ss = v.x*v.x + v.y*v.y + v.z*v.z + v.w*v.w;
    #pragma unroll
    for (int o = 16; o > 0; o >>= 1) {
        s  += __shfl_xor_sync(0xffffffffu, s,  o);
        ss += __shfl_xor_sync(0xffffffffu, ss, o);
    }
    __shared__ float shs[8], shq[8];
    int w = t >> 5, l = t & 31;
    if (l == 0) { shs[w] = s; shq[w] = ss; }
    __syncthreads();
    float S = 0.f, Q = 0.f;
    #pragma unroll
    for (int i = 0; i < 8; i++) { S += shs[i]; Q += shq[i]; }
    float mean = S * (1.f / (float)D_);
    float var  = (Q - (float)D_ * mean * mean) * (1.f / (float)(D_ - 1));
    float inv  = rsqrtf(var + 1e-9f);
    const float4 g  = ((const float4*)gamma)[t];
    const float4 be = ((const float4*)beta)[t];
    float o0 = g.x * (v.x - mean) * inv + be.x;
    float o1 = g.y * (v.y - mean) * inv + be.y;
    float o2 = g.z * (v.z - mean) * inv + be.z;
    float o3 = g.w * (v.w - mean) * inv + be.w;
    size_t idx = (size_t)row * (D_/4) + t;
    ((uint2*)yh)[idx] = make_uint2(pk2h(o0, o1), pk2h(o2, o3));
}

// ---------------- mma.sync fp16 single-term GEMM (R11 form) -----------------
// 128x128x64 CTA K-chunk, 256 threads (8 warps, 2m x 4n), 3-stage cp.async,
// single barrier per iteration, 2 CTAs/SM, XOR-swizzled smem (no pad).
#define MATB 16384   // 128 rows x 128 bytes
#define STB  (2 * MATB)
#define SMEM_GEMM (3 * STB)   // 98304

template<bool RELU, bool BIAS, bool RES, bool OUTF16>
__global__ __launch_bounds__(256, 2) void tc_gemm(
    const h16* __restrict__ Ah, const h16* __restrict__ Bh,
    const float* __restrict__ bias, const float* __restrict__ res,
    float* __restrict__ Cf, h16* __restrict__ Ch,
    int M, int N, int K)
{
    extern __shared__ char smem[];
    uint32_t sb = smem_to_u32(smem);
    int tid = threadIdx.x;
    int lane = tid & 31, wid = tid >> 5;
    int wm = wid & 1, wn = wid >> 1;
    int row0 = blockIdx.y * 128, col0 = blockIdx.x * 128;

    // ---- loader mapping: row lm (0..127), half lc (0/1 = 64B each) ----
    int lm = tid >> 1;
    int lc = tid & 1;
    const h16* aHs = Ah + (size_t)(row0 + lm) * K + lc * 32;
    const h16* bHs = Bh + (size_t)(col0 + lm) * K + lc * 32;
    uint32_t dRow = (uint32_t)(lm << 7);
    uint32_t dCol[4];
    #pragma unroll
    for (int j = 0; j < 4; j++)
        dCol[j] = (uint32_t)(((lc * 64 + j * 16) ^ ((lm & 7) << 4)));

    auto load_stage = [&](int p, int kt) {
        uint32_t s0 = sb + p * STB + dRow;
        size_t ko = (size_t)kt * 64;
        #pragma unroll
        for (int j = 0; j < 4; j++) cp16(s0 + dCol[j], aHs + ko + j * 8);
        #pragma unroll
        for (int j = 0; j < 4; j++) cp16(s0 + MATB + dCol[j], bHs + ko + j * 8);
    };

    // ---- ldmatrix per-lane offsets (swizzle term = r*16, lane-constant) ----
    int g = lane >> 3, r = lane & 7;
    uint32_t aRow[4], bRow[2];
    #pragma unroll
    for (int mt = 0; mt < 4; mt++)
        aRow[mt] = (uint32_t)((wm * 64 + mt * 16 + (g & 1) * 8 + r) << 7);
    #pragma unroll
    for (int nb = 0; nb < 2; nb++)
        bRow[nb] = (uint32_t)((wn * 32 + nb * 16 + (g >> 1) * 8 + r) << 7);
    uint32_t aColSw[4], bColSw[4];
    #pragma unroll
    for (int h = 0; h < 4; h++) {
        aColSw[h] = (uint32_t)(((h << 5) + ((g >> 1) << 4)) ^ (r << 4));
        bColSw[h] = (uint32_t)(((h << 5) + ((g & 1) << 4)) ^ (r << 4));
    }

    float acc[4][4][4];
    #pragma unroll
    for (int i = 0; i < 4; i++)
        #pragma unroll
        for (int j = 0; j < 4; j++)
            #pragma unroll
            for (int e = 0; e < 4; e++) acc[i][j][e] = 0.f;

    int KT = K / 64;
    load_stage(0, 0); CP_COMMIT();
    load_stage(1, 1); CP_COMMIT();

    int s = 0;
    for (int kt = 0; kt < KT; kt++) {
        __syncthreads();                   // stage (kt-1)%3 fully consumed
        if (kt + 2 < KT) {
            int sw = s + 2; if (sw >= 3) sw -= 3;
            load_stage(sw, kt + 2);        // overlaps with MMA below
        }
        CP_COMMIT();
        asm volatile("cp.async.wait_group 2;" ::: "memory");  // stage kt ready
        uint32_t st = sb + s * STB;
        #pragma unroll
        for (int h = 0; h < 4; h++) {
            uint32_t ah[4][4], bh[2][4];
            #pragma unroll
            for (int mt = 0; mt < 4; mt++)
                ldm4(ah[mt], st + aRow[mt] + aColSw[h]);
            #pragma unroll
            for (int nb = 0; nb < 2; nb++)
                ldm4(bh[nb], st + MATB + bRow[nb] + bColSw[h]);
            #pragma unroll
            for (int mt = 0; mt < 4; mt++)
                #pragma unroll
                for (int nt = 0; nt < 4; nt++)
                    mma_f16(acc[mt][nt], ah[mt],
                            bh[nt >> 1][(nt & 1) * 2], bh[nt >> 1][(nt & 1) * 2 + 1]);
        }
        if (++s >= 3) s = 0;
    }

    // epilogue
    #pragma unroll
    for (int mt = 0; mt < 4; mt++) {
        int r_lo = row0 + wm * 64 + mt * 16 + (lane >> 2);
        #pragma unroll
        for (int nt = 0; nt < 4; nt++) {
            int col = col0 + wn * 32 + nt * 8 + (lane & 3) * 2;
            float* d = acc[mt][nt];
            float bi0 = 0.f, bi1 = 0.f;
            if (BIAS) { bi0 = __ldg(bias + col); bi1 = __ldg(bias + col + 1); }
            #pragma unroll
            for (int half = 0; half < 2; half++) {
                int row = r_lo + half * 8;
                float v0 = d[half * 2 + 0], v1 = d[half * 2 + 1];
                if (BIAS) { v0 += bi0; v1 += bi1; }
                if (RELU) { v0 = fmaxf(v0, 0.f); v1 = fmaxf(v1, 0.f); }
                size_t base = (size_t)row * N + col;
                if (RES) {
                    float2 rr = *(const float2*)(res + base);
                    v0 += rr.x; v1 += rr.y;
                }
                if (OUTF16) {
                    *(uint32_t*)(Ch + base) = pk2h(v0, v1);
                } else {
                    *(float2*)(Cf + base) = make_float2(v0, v1);
                }
            }
        }
    }
}

// ---------------- Tensor-core flash attention (R11 form, __expf) ------------
// CTA: 128 q-rows x one head. 8 warps x 16 rows. 64-key chunks, 3-stage
// cp.async ring, single barrier per chunk, 2 CTAs/SM.
#define AROWB 144
#define A_V   9216
#define A_M   18432
#define A_STRIDE 18688
#define A_SMEM (3 * A_STRIDE)   // 56064

__global__ __launch_bounds__(256, 2) void attention_tc(
    const h16* __restrict__ qkvh, const int* __restrict__ mask,
    h16* __restrict__ oh)
{
    extern __shared__ char smem[];
    uint32_t sb = smem_to_u32(smem);
    int tid = threadIdx.x, lane = tid & 31, w = tid >> 5;
    int bh_ = blockIdx.y, b = bh_ >> 4, h = bh_ & 15;
    int q0 = blockIdx.x * 128;
    size_t hoff = (size_t)h * DKH;
    int g = lane >> 3, r = lane & 7;

    // ---- stage Q (hi only) into stage-0 region, read to regs, then reuse ---
    {
        int lm = tid >> 1;
        int lc = (tid & 1) * 4;
        size_t go = (size_t)(b * S_ + q0 + lm) * QKVS + hoff + lc * 8;
        uint32_t d0 = sb + (uint32_t)(lm * AROWB + lc * 16);
        #pragma unroll
        for (int j = 0; j < 4; j++)
            cp16(d0 + j * 16, qkvh + go + j * 8);
        CP_COMMIT();
    }
    asm volatile("cp.async.wait_group 0;" ::: "memory");
    __syncthreads();

    uint32_t Qh4[4][4];
    {
        uint32_t aoff = sb + (uint32_t)((w * 16 + (g & 1) * 8 + r) * AROWB + (g >> 1) * 16);
        #pragma unroll
        for (int ks = 0; ks < 4; ks++)
            ldm4(Qh4[ks], aoff + ks * 32);
    }
    __syncthreads();   // protect stage-0 region before K/V chunk 0 overwrites

    float m0 = -1e30f, m1 = -1e30f, l0 = 0.f, l1 = 0.f;
    float acc[8][4];
    #pragma unroll
    for (int i = 0; i < 8; i++)
        #pragma unroll
        for (int e = 0; e < 4; e++) acc[i][e] = 0.f;

    const h16* kbh = qkvh + (size_t)b * S_ * QKVS + D_ + hoff;
    const h16* vb  = qkvh + (size_t)b * S_ * QKVS + 2 * D_ + hoff;
    const int* mrow = mask + (size_t)b * S_;

    auto load_chunk = [&](int stg_i, int c) {
        uint32_t stg = sb + stg_i * A_STRIDE;
        int lm = tid >> 2;
        int lc = (tid & 3) * 2;
        size_t go = (size_t)(c * 64 + lm) * QKVS + lc * 8;
        uint32_t d = stg + (uint32_t)(lm * AROWB + lc * 16);
        cp16(d,            kbh + go);
        cp16(d + 16,       kbh + go + 8);
        cp16(d + A_V,      vb + go);
        cp16(d + A_V + 16, vb + go + 8);
        if (tid < 64)
            asm volatile("cp.async.ca.shared.global [%0], [%1], 4;"
                :: "r"(stg + A_M + tid * 4), "l"(mrow + c * 64 + tid));
    };

    const int NC = S_ / 64;   // 32
    load_chunk(0, 0); CP_COMMIT();
    load_chunk(1, 1); CP_COMMIT();

    uint32_t bKoff = (uint32_t)(((g >> 1) * 8 + r) * AROWB + (g & 1) * 16);
    uint32_t vOff  = (uint32_t)(((g & 1) * 8 + r) * AROWB + (g >> 1) * 16);

    int si = 0;
    for (int c = 0; c < NC; c++) {
        __syncthreads();                    // stage (c-1)%3 fully consumed
        if (c + 2 < NC) {
            int sw = si + 2; if (sw >= 3) sw -= 3;
            load_chunk(sw, c + 2);          // overlaps with compute below
        }
        CP_COMMIT();
        asm volatile("cp.async.wait_group 2;" ::: "memory");   // chunk c ready
        uint32_t stg = sb + si * A_STRIDE;

        float s[8][4];
        #pragma unroll
        for (int i = 0; i < 8; i++)
            #pragma unroll
            for (int e = 0; e < 4; e++) s[i][e] = 0.f;

        // S = Q K^T (single-term fp16)
        #pragma unroll
        for (int ks = 0; ks < 4; ks++) {
            #pragma unroll
            for (int nb = 0; nb < 4; nb++) {
                uint32_t bh4[4];
                ldm4(bh4, stg + bKoff + nb * (16 * AROWB) + ks * 32);
                mma_f16(s[nb*2],   Qh4[ks], bh4[0], bh4[1]);
                mma_f16(s[nb*2+1], Qh4[ks], bh4[2], bh4[3]);
            }
        }

        // scale + mask
        const int* ms = (const int*)(smem + (size_t)si * A_STRIDE + A_M);
        #pragma unroll
        for (int nt = 0; nt < 8; nt++) {
            int cc = nt * 8 + (lane & 3) * 2;
            int mv0 = ms[cc], mv1 = ms[cc + 1];
            #pragma unroll
            for (int e = 0; e < 4; e++) s[nt][e] *= 0.125f;
            if (mv0 == 0) { s[nt][0] = -1e9f; s[nt][2] = -1e9f; }
            if (mv1 == 0) { s[nt][1] = -1e9f; s[nt][3] = -1e9f; }
        }

        // online softmax (rows r and r+8 per thread)
        float mx0 = -1e30f, mx1 = -1e30f;
        #pragma unroll
        for (int nt = 0; nt < 8; nt++) {
            mx0 = fmaxf(mx0, fmaxf(s[nt][0], s[nt][1]));
            mx1 = fmaxf(mx1, fmaxf(s[nt][2], s[nt][3]));
        }
        mx0 = fmaxf(mx0, __shfl_xor_sync(0xffffffffu, mx0, 1));
        mx0 = fmaxf(mx0, __shfl_xor_sync(0xffffffffu, mx0, 2));
        mx1 = fmaxf(mx1, __shfl_xor_sync(0xffffffffu, mx1, 1));
        mx1 = fmaxf(mx1, __shfl_xor_sync(0xffffffffu, mx1, 2));
        float mn0 = fmaxf(m0, mx0), mn1 = fmaxf(m1, mx1);
        float sc0 = __expf(m0 - mn0), sc1 = __expf(m1 - mn1);
        m0 = mn0; m1 = mn1;
        float rs0 = 0.f, rs1 = 0.f;
        #pragma unroll
        for (int nt = 0; nt < 8; nt++) {
            s[nt][0] = __expf(s[nt][0] - mn0); rs0 += s[nt][0];
            s[nt][1] = __expf(s[nt][1] - mn0); rs0 += s[nt][1];
            s[nt][2] = __expf(s[nt][2] - mn1); rs1 += s[nt][2];
            s[nt][3] = __expf(s[nt][3] - mn1); rs1 += s[nt][3];
        }
        rs0 += __shfl_xor_sync(0xffffffffu, rs0, 1);
        rs0 += __shfl_xor_sync(0xffffffffu, rs0, 2);
        rs1 += __shfl_xor_sync(0xffffffffu, rs1, 1);
        rs1 += __shfl_xor_sync(0xffffffffu, rs1, 2);
        l0 = l0 * sc0 + rs0;
        l1 = l1 * sc1 + rs1;
        #pragma unroll
        for (int no = 0; no < 8; no++) {
            acc[no][0] *= sc0; acc[no][1] *= sc0;
            acc[no][2] *= sc1; acc[no][3] *= sc1;
        }

        // O += P V   (P fragments repacked directly as A operand)
        #pragma unroll
        for (int kb = 0; kb < 4; kb++) {
            uint32_t a4[4];
            a4[0] = pk2h(s[kb*2][0],   s[kb*2][1]);
            a4[1] = pk2h(s[kb*2][2],   s[kb*2][3]);
            a4[2] = pk2h(s[kb*2+1][0], s[kb*2+1][1]);
            a4[3] = pk2h(s[kb*2+1][2], s[kb*2+1][3]);
            #pragma unroll
            for (int db = 0; db < 4; db++) {
                uint32_t bv[4];
                ldm4t(bv, stg + A_V + vOff + kb * (16 * AROWB) + db * 32);
                mma_f16(acc[db*2],   a4, bv[0], bv[1]);
                mma_f16(acc[db*2+1], a4, bv[2], bv[3]);
            }
        }

        if (++si >= 3) si = 0;
    }

    // ---- output: O / l -> fp16 (hi only) ----
    float inv0 = 1.f / l0, inv1 = 1.f / l1;
    int row0 = q0 + w * 16 + (lane >> 2);
    size_t t0 = (size_t)(b * S_ + row0) * D_ + hoff;
    size_t t1 = t0 + (size_t)8 * D_;
    #pragma unroll
    for (int no = 0; no < 8; no++) {
        int cc = no * 8 + (lane & 3) * 2;
        *(uint32_t*)(oh + t0 + cc) = pk2h(acc[no][0] * inv0, acc[no][1] * inv0);
        *(uint32_t*)(oh + t1 + cc) = pk2h(acc[no][2] * inv1, acc[no][3] * inv1);
    }
}

// ---------------- launch ----------------------------------------------------
extern "C" void kernel_launch(void* const* d_in, const int* in_sizes, int n_in,
                              void* d_out, int out_size)
{
    (void)in_sizes; (void)n_in; (void)out_size;
    const float* x    = (const float*)d_in[0];
    const int*   mask = (const int*)  d_in[1];
    const float* wq   = (const float*)d_in[2];
    const float* wk   = (const float*)d_in[3];
    const float* wv   = (const float*)d_in[4];
    const float* wo   = (const float*)d_in[5];
    const float* w1   = (const float*)d_in[6];
    const float* b1   = (const float*)d_in[7];
    const float* w2   = (const float*)d_in[8];
    const float* b2   = (const float*)d_in[9];
    const float* g1   = (const float*)d_in[10];
    const float* be1  = (const float*)d_in[11];
    const float* g2   = (const float*)d_in[12];
    const float* be2  = (const float*)d_in[13];
    float* out = (float*)d_out;

    float *h1;
    h16 *zh, *qkvh, *ah, *mh;
    h16 *wc, *wop, *w1p, *w2p;
    cudaGetSymbolAddress((void**)&h1, g_h1);
    cudaGetSymbolAddress((void**)&zh, g_zh);
    cudaGetSymbolAddress((void**)&qkvh, g_qkvh);
    cudaGetSymbolAddress((void**)&ah, g_ah);
    cudaGetSymbolAddress((void**)&mh, g_mh);
    cudaGetSymbolAddress((void**)&wc, g_wc);
    cudaGetSymbolAddress((void**)&wop, g_wo);
    cudaGetSymbolAddress((void**)&w1p, g_w1);
    cudaGetSymbolAddress((void**)&w2p, g_w2);

    cudaFuncSetAttribute(tc_gemm<false,false,false,true >, cudaFuncAttributeMaxDynamicSharedMemorySize, SMEM_GEMM);
    cudaFuncSetAttribute(tc_gemm<false,false,true ,false>, cudaFuncAttributeMaxDynamicSharedMemorySize, SMEM_GEMM);
    cudaFuncSetAttribute(tc_gemm<true ,true ,false,true >, cudaFuncAttributeMaxDynamicSharedMemorySize, SMEM_GEMM);
    cudaFuncSetAttribute(tc_gemm<false,true ,true ,false>, cudaFuncAttributeMaxDynamicSharedMemorySize, SMEM_GEMM);
    cudaFuncSetAttribute(attention_tc, cudaFuncAttributeMaxDynamicSharedMemorySize, A_SMEM);

    // 1: fused weight conversions (single launch)
    convert_all<<<12288, 256>>>(wq, wk, wv, wo, w1, w2, wc, wop, w1p, w2p);

    // 2: LN1 -> fp16
    layernorm_kernel<<<NT, 256>>>(x, g1, be1, zh);

    // 3: fused QKV GEMM (N = 3072) -> fp16
    dim3 gQKV(QKVS / 128, NT / 128);
    tc_gemm<false,false,false,true><<<gQKV, 256, SMEM_GEMM>>>(
        zh, wc, nullptr, nullptr, nullptr, qkvh, NT, QKVS, D_);

    // 4: attention (tensor core) -> fp16
    dim3 gAtt(S_ / 128, B_ * H_);
    attention_tc<<<gAtt, 256, A_SMEM>>>(qkvh, mask, ah);

    // 5: h1 = x + attn @ wo^T
    dim3 gP(D_ / 128, NT / 128);
    tc_gemm<false,false,true,false><<<gP, 256, SMEM_GEMM>>>(
        ah, wop, nullptr, x, h1, nullptr, NT, D_, D_);

    // 6: LN2 -> fp16
    layernorm_kernel<<<NT, 256>>>(h1, g2, be2, zh);

    // 7: FFN1: mid = relu(z @ w1^T + b1) -> fp16
    dim3 gF1(DFF_ / 128, NT / 128);
    tc_gemm<true,true,false,true><<<gF1, 256, SMEM_GEMM>>>(
        zh, w1p, b1, nullptr, nullptr, mh, NT, DFF_, D_);

    // 8: FFN2: out = h1 + mid @ w2^T + b2
    dim3 gF2(D_ / 128, NT / 128);
    tc_gemm<false,true,true,false><<<gF2, 256, SMEM_GEMM>>>(
        mh, w2p, b2, h1, out, nullptr, NT, D_, DFF_);
}

// round 16
// speedup vs baseline: 1.0551x; 1.0015x over previous
#include <cuda_runtime.h>
#include <cuda_fp16.h>
#include <math.h>
#include <stdint.h>

// Problem dims
#define B_  4
#define S_  2048
#define D_  1024
#define H_  16
#define DKH 64
#define DFF_ 4096
#define NT  (B_ * S_)   // 8192 tokens
#define QKVS 3072       // fused qkv row stride

typedef __half h16;

// ====================== PTX helpers (baseline ISA, sm_80+) ==================
__device__ __forceinline__ uint32_t smem_to_u32(const void* p) {
    uint32_t a;
    asm("{ .reg .u64 t; cvta.to.shared.u64 t, %1; cvt.u32.u64 %0, t; }" : "=r"(a) : "l"(p));
    return a;
}
__device__ __forceinline__ void cp16(uint32_t dst, const void* src) {
    asm volatile("cp.async.cg.shared.global [%0], [%1], 16;" :: "r"(dst), "l"(src));
}
#define CP_COMMIT() asm volatile("cp.async.commit_group;" ::: "memory")

__device__ __forceinline__ void ldm4(uint32_t* r, uint32_t addr) {
    asm volatile("ldmatrix.sync.aligned.m8n8.x4.shared.b16 {%0,%1,%2,%3}, [%4];"
        : "=r"(r[0]), "=r"(r[1]), "=r"(r[2]), "=r"(r[3]) : "r"(addr));
}
__device__ __forceinline__ void ldm4t(uint32_t* r, uint32_t addr) {
    asm volatile("ldmatrix.sync.aligned.m8n8.x4.trans.shared.b16 {%0,%1,%2,%3}, [%4];"
        : "=r"(r[0]), "=r"(r[1]), "=r"(r[2]), "=r"(r[3]) : "r"(addr));
}
__device__ __forceinline__ void mma_f16(float* d, const uint32_t* a,
                                        uint32_t b0, uint32_t b1) {
    asm volatile(
        "mma.sync.aligned.m16n8k16.row.col.f32.f16.f16.f32 "
        "{%0,%1,%2,%3}, {%4,%5,%6,%7}, {%8,%9}, {%0,%1,%2,%3};"
        : "+f"(d[0]), "+f"(d[1]), "+f"(d[2]), "+f"(d[3])
        : "r"(a[0]), "r"(a[1]), "r"(a[2]), "r"(a[3]), "r"(b0), "r"(b1));
}

__device__ __forceinline__ uint32_t pk2h(float a, float b) {
    return (uint32_t)__half_as_ushort(__float2half_rn(a)) |
           ((uint32_t)__half_as_ushort(__float2half_rn(b)) << 16);
}

// ---------------- scratch (device globals) ----------------------------------
__device__ __align__(256) float g_h1[(size_t)NT * D_];
__device__ __align__(256) h16 g_zh[(size_t)NT * D_];
__device__ __align__(256) h16 g_qkvh[(size_t)NT * QKVS];
__device__ __align__(256) h16 g_ah[(size_t)NT * D_];
__device__ __align__(256) h16 g_mh[(size_t)NT * DFF_];
__device__ __align__(256) h16 g_wc[(size_t)3*D_*D_];
__device__ __align__(256) h16 g_wo[(size_t)D_*D_];
__device__ __align__(256) h16 g_w1[(size_t)DFF_*D_];
__device__ __align__(256) h16 g_w2[(size_t)D_*DFF_];

// ---------------- single fused weight convert --------------------------------
// wq is pre-scaled by 0.125 (= 1/sqrt(dk)); x2^-3 only shifts the fp16
// exponent, so fp16(0.125*w) == 0.125*fp16(w) exactly -> scores arrive
// pre-scaled with zero extra rounding.
__global__ __launch_bounds__(256) void convert_all(
    const float* __restrict__ wq, const float* __restrict__ wk,
    const float* __restrict__ wv, const float* __restrict__ wo,
    const float* __restrict__ w1, const float* __restrict__ w2,
    h16* __restrict__ wc, h16* __restrict__ dwo,
    h16* __restrict__ dw1, h16* __restrict__ dw2)
{
    int bx = blockIdx.x;
    const float* src; h16* dst; int i;
    float scl = 1.0f;
    if (bx < 1024)      { src = wq; dst = wc;                       i = bx * 256 + threadIdx.x; scl = 0.125f; }
    else if (bx < 2048) { src = wk; dst = wc + (size_t)D_*D_;       i = (bx-1024) * 256 + threadIdx.x; }
    else if (bx < 3072) { src = wv; dst = wc + (size_t)2*D_*D_;     i = (bx-2048) * 256 + threadIdx.x; }
    else if (bx < 4096) { src = wo; dst = dwo;                      i = (bx-3072) * 256 + threadIdx.x; }
    else if (bx < 8192) { src = w1; dst = dw1;                      i = (bx-4096) * 256 + threadIdx.x; }
    else                { src = w2; dst = dw2;                      i = (bx-8192) * 256 + threadIdx.x; }
    float4 v = ((const float4*)src)[i];
    v.x *= scl; v.y *= scl; v.z *= scl; v.w *= scl;
    ((uint2*)dst)[i] = make_uint2(pk2h(v.x, v.y), pk2h(v.z, v.w));
}

// ---------------- LayerNorm (Bessel ddof=1, eps=1e-9) -> fp16 ---------------
__global__ __launch_bounds__(256) void layernorm_kernel(
    const float* __restrict__ x, const float* __restrict__ gamma,
    const float* __restrict__ beta, h16* __restrict__ yh)
{
    int row = blockIdx.x;
    int t = threadIdx.x;
    const float4* xr = (const float4*)(x + (size_t)row * D_);
    float4 v = xr[t];
    float s  = v.x + v.y + v.z + v.w;
    float ss = v.x*v.x + v.y*v.y + v.z*v.z + v.w*v.w;
    #pragma unroll
    for (int o = 16; o > 0; o >>= 1) {
        s  += __shfl_xor_sync(0xffffffffu, s,  o);
        ss += __shfl_xor_sync(0xffffffffu, ss, o);
    }
    __shared__ float shs[8], shq[8];
    int w = t >> 5, l = t & 31;
    if (l == 0) { shs[w] = s; shq[w] = ss; }
    __syncthreads();
    float S = 0.f, Q = 0.f;
    #pragma unroll
    for (int i = 0; i < 8; i++) { S += shs[i]; Q += shq[i]; }
    float mean = S * (1.f / (float)D_);
    float var  = (Q - (float)D_ * mean * mean) * (1.f / (float)(D_ - 1));
    float inv  = rsqrtf(var + 1e-9f);
    const float4 g  = ((const float4*)gamma)[t];
    const float4 be = ((const float4*)beta)[t];
    float o0 = g.x * (v.x - mean) * inv + be.x;
    float o1 = g.y * (v.y - mean) * inv + be.y;
    float o2 = g.z * (v.z - mean) * inv + be.z;
    float o3 = g.w * (v.w - mean) * inv + be.w;
    size_t idx = (size_t)row * (D_/4) + t;
    ((uint2*)yh)[idx] = make_uint2(pk2h(o0, o1), pk2h(o2, o3));
}

// ---------------- mma.sync fp16 single-term GEMM (R11 form) -----------------
// 128x128x64 CTA K-chunk, 256 threads (8 warps, 2m x 4n), 3-stage cp.async,
// single barrier per iteration, 2 CTAs/SM, XOR-swizzled smem (no pad).
#define MATB 16384   // 128 rows x 128 bytes
#define STB  (2 * MATB)
#define SMEM_GEMM (3 * STB)   // 98304

template<bool RELU, bool BIAS, bool RES, bool OUTF16>
__global__ __launch_bounds__(256, 2) void tc_gemm(
    const h16* __restrict__ Ah, const h16* __restrict__ Bh,
    const float* __restrict__ bias, const float* __restrict__ res,
    float* __restrict__ Cf, h16* __restrict__ Ch,
    int M, int N, int K)
{
    extern __shared__ char smem[];
    uint32_t sb = smem_to_u32(smem);
    int tid = threadIdx.x;
    int lane = tid & 31, wid = tid >> 5;
    int wm = wid & 1, wn = wid >> 1;
    int row0 = blockIdx.y * 128, col0 = blockIdx.x * 128;

    // ---- loader mapping: row lm (0..127), half lc (0/1 = 64B each) ----
    int lm = tid >> 1;
    int lc = tid & 1;
    const h16* aHs = Ah + (size_t)(row0 + lm) * K + lc * 32;
    const h16* bHs = Bh + (size_t)(col0 + lm) * K + lc * 32;
    uint32_t dRow = (uint32_t)(lm << 7);
    uint32_t dCol[4];
    #pragma unroll
    for (int j = 0; j < 4; j++)
        dCol[j] = (uint32_t)(((lc * 64 + j * 16) ^ ((lm & 7) << 4)));

    auto load_stage = [&](int p, int kt) {
        uint32_t s0 = sb + p * STB + dRow;
        size_t ko = (size_t)kt * 64;
        #pragma unroll
        for (int j = 0; j < 4; j++) cp16(s0 + dCol[j], aHs + ko + j * 8);
        #pragma unroll
        for (int j = 0; j < 4; j++) cp16(s0 + MATB + dCol[j], bHs + ko + j * 8);
    };

    // ---- ldmatrix per-lane offsets (swizzle term = r*16, lane-constant) ----
    int g = lane >> 3, r = lane & 7;
    uint32_t aRow[4], bRow[2];
    #pragma unroll
    for (int mt = 0; mt < 4; mt++)
        aRow[mt] = (uint32_t)((wm * 64 + mt * 16 + (g & 1) * 8 + r) << 7);
    #pragma unroll
    for (int nb = 0; nb < 2; nb++)
        bRow[nb] = (uint32_t)((wn * 32 + nb * 16 + (g >> 1) * 8 + r) << 7);
    uint32_t aColSw[4], bColSw[4];
    #pragma unroll
    for (int h = 0; h < 4; h++) {
        aColSw[h] = (uint32_t)(((h << 5) + ((g >> 1) << 4)) ^ (r << 4));
        bColSw[h] = (uint32_t)(((h << 5) + ((g & 1) << 4)) ^ (r << 4));
    }

    float acc[4][4][4];
    #pragma unroll
    for (int i = 0; i < 4; i++)
        #pragma unroll
        for (int j = 0; j < 4; j++)
            #pragma unroll
            for (int e = 0; e < 4; e++) acc[i][j][e] = 0.f;

    int KT = K / 64;
    load_stage(0, 0); CP_COMMIT();
    load_stage(1, 1); CP_COMMIT();

    int s = 0;
    for (int kt = 0; kt < KT; kt++) {
        __syncthreads();                   // stage (kt-1)%3 fully consumed
        if (kt + 2 < KT) {
            int sw = s + 2; if (sw >= 3) sw -= 3;
            load_stage(sw, kt + 2);        // overlaps with MMA below
        }
        CP_COMMIT();
        asm volatile("cp.async.wait_group 2;" ::: "memory");  // stage kt ready
        uint32_t st = sb + s * STB;
        #pragma unroll
        for (int h = 0; h < 4; h++) {
            uint32_t ah[4][4], bh[2][4];
            #pragma unroll
            for (int mt = 0; mt < 4; mt++)
                ldm4(ah[mt], st + aRow[mt] + aColSw[h]);
            #pragma unroll
            for (int nb = 0; nb < 2; nb++)
                ldm4(bh[nb], st + MATB + bRow[nb] + bColSw[h]);
            #pragma unroll
            for (int mt = 0; mt < 4; mt++)
                #pragma unroll
                for (int nt = 0; nt < 4; nt++)
                    mma_f16(acc[mt][nt], ah[mt],
                            bh[nt >> 1][(nt & 1) * 2], bh[nt >> 1][(nt & 1) * 2 + 1]);
        }
        if (++s >= 3) s = 0;
    }

    // epilogue
    #pragma unroll
    for (int mt = 0; mt < 4; mt++) {
        int r_lo = row0 + wm * 64 + mt * 16 + (lane >> 2);
        #pragma unroll
        for (int nt = 0; nt < 4; nt++) {
            int col = col0 + wn * 32 + nt * 8 + (lane & 3) * 2;
            float* d = acc[mt][nt];
            float bi0 = 0.f, bi1 = 0.f;
            if (BIAS) { bi0 = __ldg(bias + col); bi1 = __ldg(bias + col + 1); }
            #pragma unroll
            for (int half = 0; half < 2; half++) {
                int row = r_lo + half * 8;
                float v0 = d[half * 2 + 0], v1 = d[half * 2 + 1];
                if (BIAS) { v0 += bi0; v1 += bi1; }
                if (RELU) { v0 = fmaxf(v0, 0.f); v1 = fmaxf(v1, 0.f); }
                size_t base = (size_t)row * N + col;
                if (RES) {
                    float2 rr = *(const float2*)(res + base);
                    v0 += rr.x; v1 += rr.y;
                }
                if (OUTF16) {
                    *(uint32_t*)(Ch + base) = pk2h(v0, v1);
                } else {
                    *(float2*)(Cf + base) = make_float2(v0, v1);
                }
            }
        }
    }
}

// ---------------- Tensor-core flash attention (scores pre-scaled) -----------
// CTA: 128 q-rows x one head. 8 warps x 16 rows. 64-key chunks, 3-stage
// cp.async ring, single barrier per chunk, 2 CTAs/SM. Q pre-scaled via wq.
#define AROWB 144
#define A_V   9216
#define A_M   18432
#define A_STRIDE 18688
#define A_SMEM (3 * A_STRIDE)   // 56064

__global__ __launch_bounds__(256, 2) void attention_tc(
    const h16* __restrict__ qkvh, const int* __restrict__ mask,
    h16* __restrict__ oh)
{
    extern __shared__ char smem[];
    uint32_t sb = smem_to_u32(smem);
    int tid = threadIdx.x, lane = tid & 31, w = tid >> 5;
    int bh_ = blockIdx.y, b = bh_ >> 4, h = bh_ & 15;
    int q0 = blockIdx.x * 128;
    size_t hoff = (size_t)h * DKH;
    int g = lane >> 3, r = lane & 7;

    // ---- stage Q (hi only) into stage-0 region, read to regs, then reuse ---
    {
        int lm = tid >> 1;
        int lc = (tid & 1) * 4;
        size_t go = (size_t)(b * S_ + q0 + lm) * QKVS + hoff + lc * 8;
        uint32_t d0 = sb + (uint32_t)(lm * AROWB + lc * 16);
        #pragma unroll
        for (int j = 0; j < 4; j++)
            cp16(d0 + j * 16, qkvh + go + j * 8);
        CP_COMMIT();
    }
    asm volatile("cp.async.wait_group 0;" ::: "memory");
    __syncthreads();

    uint32_t Qh4[4][4];
    {
        uint32_t aoff = sb + (uint32_t)((w * 16 + (g & 1) * 8 + r) * AROWB + (g >> 1) * 16);
        #pragma unroll
        for (int ks = 0; ks < 4; ks++)
            ldm4(Qh4[ks], aoff + ks * 32);
    }
    __syncthreads();   // protect stage-0 region before K/V chunk 0 overwrites

    float m0 = -1e30f, m1 = -1e30f, l0 = 0.f, l1 = 0.f;
    float acc[8][4];
    #pragma unroll
    for (int i = 0; i < 8; i++)
        #pragma unroll
        for (int e = 0; e < 4; e++) acc[i][e] = 0.f;

    const h16* kbh = qkvh + (size_t)b * S_ * QKVS + D_ + hoff;
    const h16* vb  = qkvh + (size_t)b * S_ * QKVS + 2 * D_ + hoff;
    const int* mrow = mask + (size_t)b * S_;

    auto load_chunk = [&](int stg_i, int c) {
        uint32_t stg = sb + stg_i * A_STRIDE;
        int lm = tid >> 2;
        int lc = (tid & 3) * 2;
        size_t go = (size_t)(c * 64 + lm) * QKVS + lc * 8;
        uint32_t d = stg + (uint32_t)(lm * AROWB + lc * 16);
        cp16(d,            kbh + go);
        cp16(d + 16,       kbh + go + 8);
        cp16(d + A_V,      vb + go);
        cp16(d + A_V + 16, vb + go + 8);
        if (tid < 64)
            asm volatile("cp.async.ca.shared.global [%0], [%1], 4;"
                :: "r"(stg + A_M + tid * 4), "l"(mrow + c * 64 + tid));
    };

    const int NC = S_ / 64;   // 32
    load_chunk(0, 0); CP_COMMIT();
    load_chunk(1, 1); CP_COMMIT();

    uint32_t bKoff = (uint32_t)(((g >> 1) * 8 + r) * AROWB + (g & 1) * 16);
    uint32_t vOff  = (uint32_t)(((g & 1) * 8 + r) * AROWB + (g >> 1) * 16);

    int si = 0;
    for (int c = 0; c < NC; c++) {
        __syncthreads();                    // stage (c-1)%3 fully consumed
        if (c + 2 < NC) {
            int sw = si + 2; if (sw >= 3) sw -= 3;
            load_chunk(sw, c + 2);          // overlaps with compute below
        }
        CP_COMMIT();
        asm volatile("cp.async.wait_group 2;" ::: "memory");   // chunk c ready
        uint32_t stg = sb + si * A_STRIDE;

        float s[8][4];
        #pragma unroll
        for (int i = 0; i < 8; i++)
            #pragma unroll
            for (int e = 0; e < 4; e++) s[i][e] = 0.f;

        // S = Q K^T (single-term fp16; scores arrive pre-scaled by 1/8)
        #pragma unroll
        for (int ks = 0; ks < 4; ks++) {
            #pragma unroll
            for (int nb = 0; nb < 4; nb++) {
                uint32_t bh4[4];
                ldm4(bh4, stg + bKoff + nb * (16 * AROWB) + ks * 32);
                mma_f16(s[nb*2],   Qh4[ks], bh4[0], bh4[1]);
                mma_f16(s[nb*2+1], Qh4[ks], bh4[2], bh4[3]);
            }
        }

        // mask (scores already scaled)
        const int* ms = (const int*)(smem + (size_t)si * A_STRIDE + A_M);
        #pragma unroll
        for (int nt = 0; nt < 8; nt++) {
            int cc = nt * 8 + (lane & 3) * 2;
            int mv0 = ms[cc], mv1 = ms[cc + 1];
            if (mv0 == 0) { s[nt][0] = -1e9f; s[nt][2] = -1e9f; }
            if (mv1 == 0) { s[nt][1] = -1e9f; s[nt][3] = -1e9f; }
        }

        // online softmax (rows r and r+8 per thread)
        float mx0 = -1e30f, mx1 = -1e30f;
        #pragma unroll
        for (int nt = 0; nt < 8; nt++) {
            mx0 = fmaxf(mx0, fmaxf(s[nt][0], s[nt][1]));
            mx1 = fmaxf(mx1, fmaxf(s[nt][2], s[nt][3]));
        }
        mx0 = fmaxf(mx0, __shfl_xor_sync(0xffffffffu, mx0, 1));
        mx0 = fmaxf(mx0, __shfl_xor_sync(0xffffffffu, mx0, 2));
        mx1 = fmaxf(mx1, __shfl_xor_sync(0xffffffffu, mx1, 1));
        mx1 = fmaxf(mx1, __shfl_xor_sync(0xffffffffu, mx1, 2));
        float mn0 = fmaxf(m0, mx0), mn1 = fmaxf(m1, mx1);
        float sc0 = __expf(m0 - mn0), sc1 = __expf(m1 - mn1);
        m0 = mn0; m1 = mn1;
        float rs0 = 0.f, rs1 = 0.f;
        #pragma unroll
        for (int nt = 0; nt < 8; nt++) {
            s[nt][0] = __expf(s[nt][0] - mn0); rs0 += s[nt][0];
            s[nt][1] = __expf(s[nt][1] - mn0); rs0 += s[nt][1];
            s[nt][2] = __expf(s[nt][2] - mn1); rs1 += s[nt][2];
            s[nt][3] = __expf(s[nt][3] - mn1); rs1 += s[nt][3];
        }
        rs0 += __shfl_xor_sync(0xffffffffu, rs0, 1);
        rs0 += __shfl_xor_sync(0xffffffffu, rs0, 2);
        rs1 += __shfl_xor_sync(0xffffffffu, rs1, 1);
        rs1 += __shfl_xor_sync(0xffffffffu, rs1, 2);
        l0 = l0 * sc0 + rs0;
        l1 = l1 * sc1 + rs1;
        #pragma unroll
        for (int no = 0; no < 8; no++) {
            acc[no][0] *= sc0; acc[no][1] *= sc0;
            acc[no][2] *= sc1; acc[no][3] *= sc1;
        }

        // O += P V   (P fragments repacked directly as A operand)
        #pragma unroll
        for (int kb = 0; kb < 4; kb++) {
            uint32_t a4[4];
            a4[0] = pk2h(s[kb*2][0],   s[kb*2][1]);
            a4[1] = pk2h(s[kb*2][2],   s[kb*2][3]);
            a4[2] = pk2h(s[kb*2+1][0], s[kb*2+1][1]);
            a4[3] = pk2h(s[kb*2+1][2], s[kb*2+1][3]);
            #pragma unroll
            for (int db = 0; db < 4; db++) {
                uint32_t bv[4];
                ldm4t(bv, stg + A_V + vOff + kb * (16 * AROWB) + db * 32);
                mma_f16(acc[db*2],   a4, bv[0], bv[1]);
                mma_f16(acc[db*2+1], a4, bv[2], bv[3]);
            }
        }

        if (++si >= 3) si = 0;
    }

    // ---- output: O / l -> fp16 (hi only) ----
    float inv0 = 1.f / l0, inv1 = 1.f / l1;
    int row0 = q0 + w * 16 + (lane >> 2);
    size_t t0 = (size_t)(b * S_ + row0) * D_ + hoff;
    size_t t1 = t0 + (size_t)8 * D_;
    #pragma unroll
    for (int no = 0; no < 8; no++) {
        int cc = no * 8 + (lane & 3) * 2;
        *(uint32_t*)(oh + t0 + cc) = pk2h(acc[no][0] * inv0, acc[no][1] * inv0);
        *(uint32_t*)(oh + t1 + cc) = pk2h(acc[no][2] * inv1, acc[no][3] * inv1);
    }
}

// ---------------- launch ----------------------------------------------------
extern "C" void kernel_launch(void* const* d_in, const int* in_sizes, int n_in,
                              void* d_out, int out_size)
{
    (void)in_sizes; (void)n_in; (void)out_size;
    const float* x    = (const float*)d_in[0];
    const int*   mask = (const int*)  d_in[1];
    const float* wq   = (const float*)d_in[2];
    const float* wk   = (const float*)d_in[3];
    const float* wv   = (const float*)d_in[4];
    const float* wo   = (const float*)d_in[5];
    const float* w1   = (const float*)d_in[6];
    const float* b1   = (const float*)d_in[7];
    const float* w2   = (const float*)d_in[8];
    const float* b2   = (const float*)d_in[9];
    const float* g1   = (const float*)d_in[10];
    const float* be1  = (const float*)d_in[11];
    const float* g2   = (const float*)d_in[12];
    const float* be2  = (const float*)d_in[13];
    float* out = (float*)d_out;

    float *h1;
    h16 *zh, *qkvh, *ah, *mh;
    h16 *wc, *wop, *w1p, *w2p;
    cudaGetSymbolAddress((void**)&h1, g_h1);
    cudaGetSymbolAddress((void**)&zh, g_zh);
    cudaGetSymbolAddress((void**)&qkvh, g_qkvh);
    cudaGetSymbolAddress((void**)&ah, g_ah);
    cudaGetSymbolAddress((void**)&mh, g_mh);
    cudaGetSymbolAddress((void**)&wc, g_wc);
    cudaGetSymbolAddress((void**)&wop, g_wo);
    cudaGetSymbolAddress((void**)&w1p, g_w1);
    cudaGetSymbolAddress((void**)&w2p, g_w2);

    cudaFuncSetAttribute(tc_gemm<false,false,false,true >, cudaFuncAttributeMaxDynamicSharedMemorySize, SMEM_GEMM);
    cudaFuncSetAttribute(tc_gemm<false,false,true ,false>, cudaFuncAttributeMaxDynamicSharedMemorySize, SMEM_GEMM);
    cudaFuncSetAttribute(tc_gemm<true ,true ,false,true >, cudaFuncAttributeMaxDynamicSharedMemorySize, SMEM_GEMM);
    cudaFuncSetAttribute(tc_gemm<false,true ,true ,false>, cudaFuncAttributeMaxDynamicSharedMemorySize, SMEM_GEMM);
    cudaFuncSetAttribute(attention_tc, cudaFuncAttributeMaxDynamicSharedMemorySize, A_SMEM);

    // 1: fused weight conversions (single launch; wq pre-scaled by 1/8)
    convert_all<<<12288, 256>>>(wq, wk, wv, wo, w1, w2, wc, wop, w1p, w2p);

    // 2: LN1 -> fp16
    layernorm_kernel<<<NT, 256>>>(x, g1, be1, zh);

    // 3: fused QKV GEMM (N = 3072) -> fp16
    dim3 gQKV(QKVS / 128, NT / 128);
    tc_gemm<false,false,false,true><<<gQKV, 256, SMEM_GEMM>>>(
        zh, wc, nullptr, nullptr, nullptr, qkvh, NT, QKVS, D_);

    // 4: attention (tensor core) -> fp16
    dim3 gAtt(S_ / 128, B_ * H_);
    attention_tc<<<gAtt, 256, A_SMEM>>>(qkvh, mask, ah);

    // 5: h1 = x + attn @ wo^T
    dim3 gP(D_ / 128, NT / 128);
    tc_gemm<false,false,true,false><<<gP, 256, SMEM_GEMM>>>(
        ah, wop, nullptr, x, h1, nullptr, NT, D_, D_);

    // 6: LN2 -> fp16
    layernorm_kernel<<<NT, 256>>>(h1, g2, be2, zh);

    // 7: FFN1: mid = relu(z @ w1^T + b1) -> fp16
    dim3 gF1(DFF_ / 128, NT / 128);
    tc_gemm<true,true,false,true><<<gF1, 256, SMEM_GEMM>>>(
        zh, w1p, b1, nullptr, nullptr, mh, NT, DFF_, D_);

    // 8: FFN2: out = h1 + mid @ w2^T + b2
    dim3 gF2(D_ / 128, NT / 128);
    tc_gemm<false,true,true,false><<<gF2, 256, SMEM_GEMM>>>(
        mh, w2p, b2, h1, out, nullptr, NT, D_, DFF_);
}

// round 17
// speedup vs baseline: 1.0612x; 1.0059x over previous
#include <cuda_runtime.h>
#include <cuda_fp16.h>
#include <math.h>
#include <stdint.h>

// Problem dims
#define B_  4
#define S_  2048
#define D_  1024
#define H_  16
#define DKH 64
#define DFF_ 4096
#define NT  (B_ * S_)   // 8192 tokens
#define QKVS 3072       // fused qkv row stride

typedef __half h16;

// ====================== PTX helpers (baseline ISA, sm_80+) ==================
__device__ __forceinline__ uint32_t smem_to_u32(const void* p) {
    uint32_t a;
    asm("{ .reg .u64 t; cvta.to.shared.u64 t, %1; cvt.u32.u64 %0, t; }" : "=r"(a) : "l"(p));
    return a;
}
__device__ __forceinline__ void cp16(uint32_t dst, const void* src) {
    asm volatile("cp.async.cg.shared.global [%0], [%1], 16;" :: "r"(dst), "l"(src));
}
#define CP_COMMIT() asm volatile("cp.async.commit_group;" ::: "memory")

__device__ __forceinline__ void ldm4(uint32_t* r, uint32_t addr) {
    asm volatile("ldmatrix.sync.aligned.m8n8.x4.shared.b16 {%0,%1,%2,%3}, [%4];"
        : "=r"(r[0]), "=r"(r[1]), "=r"(r[2]), "=r"(r[3]) : "r"(addr));
}
__device__ __forceinline__ void ldm4t(uint32_t* r, uint32_t addr) {
    asm volatile("ldmatrix.sync.aligned.m8n8.x4.trans.shared.b16 {%0,%1,%2,%3}, [%4];"
        : "=r"(r[0]), "=r"(r[1]), "=r"(r[2]), "=r"(r[3]) : "r"(addr));
}
__device__ __forceinline__ void mma_f16(float* d, const uint32_t* a,
                                        uint32_t b0, uint32_t b1) {
    asm volatile(
        "mma.sync.aligned.m16n8k16.row.col.f32.f16.f16.f32 "
        "{%0,%1,%2,%3}, {%4,%5,%6,%7}, {%8,%9}, {%0,%1,%2,%3};"
        : "+f"(d[0]), "+f"(d[1]), "+f"(d[2]), "+f"(d[3])
        : "r"(a[0]), "r"(a[1]), "r"(a[2]), "r"(a[3]), "r"(b0), "r"(b1));
}

__device__ __forceinline__ uint32_t pk2h(float a, float b) {
    return (uint32_t)__half_as_ushort(__float2half_rn(a)) |
           ((uint32_t)__half_as_ushort(__float2half_rn(b)) << 16);
}

// ---------------- scratch (device globals) ----------------------------------
__device__ __align__(256) float g_h1[(size_t)NT * D_];
__device__ __align__(256) h16 g_zh[(size_t)NT * D_];
__device__ __align__(256) h16 g_qkvh[(size_t)NT * QKVS];
__device__ __align__(256) h16 g_ah[(size_t)NT * D_];
__device__ __align__(256) h16 g_mh[(size_t)NT * DFF_];
__device__ __align__(256) h16 g_wc[(size_t)3*D_*D_];
__device__ __align__(256) h16 g_wo[(size_t)D_*D_];
__device__ __align__(256) h16 g_w1[(size_t)DFF_*D_];
__device__ __align__(256) h16 g_w2[(size_t)D_*DFF_];

// ---------------- fused prep: weight converts + LN1 -------------------------
// Blocks [0,12288): convert weights (wq pre-scaled by 1/8 — exponent-only,
// exact). Blocks [12288, 12288+NT): LN1 rows -> zh.
__global__ __launch_bounds__(256) void prep_kernel(
    const float* __restrict__ wq, const float* __restrict__ wk,
    const float* __restrict__ wv, const float* __restrict__ wo,
    const float* __restrict__ w1, const float* __restrict__ w2,
    h16* __restrict__ wc, h16* __restrict__ dwo,
    h16* __restrict__ dw1, h16* __restrict__ dw2,
    const float* __restrict__ x, const float* __restrict__ gamma,
    const float* __restrict__ beta, h16* __restrict__ yh)
{
    int bx = blockIdx.x;
    if (bx < 12288) {
        const float* src; h16* dst; int i;
        float scl = 1.0f;
        if (bx < 1024)      { src = wq; dst = wc;                   i = bx * 256 + threadIdx.x; scl = 0.125f; }
        else if (bx < 2048) { src = wk; dst = wc + (size_t)D_*D_;   i = (bx-1024) * 256 + threadIdx.x; }
        else if (bx < 3072) { src = wv; dst = wc + (size_t)2*D_*D_; i = (bx-2048) * 256 + threadIdx.x; }
        else if (bx < 4096) { src = wo; dst = dwo;                  i = (bx-3072) * 256 + threadIdx.x; }
        else if (bx < 8192) { src = w1; dst = dw1;                  i = (bx-4096) * 256 + threadIdx.x; }
        else                { src = w2; dst = dw2;                  i = (bx-8192) * 256 + threadIdx.x; }
        float4 v = ((const float4*)src)[i];
        v.x *= scl; v.y *= scl; v.z *= scl; v.w *= scl;
        ((uint2*)dst)[i] = make_uint2(pk2h(v.x, v.y), pk2h(v.z, v.w));
        return;
    }
    // ---- LN1 path ----
    int row = bx - 12288;
    int t = threadIdx.x;
    const float4* xr = (const float4*)(x + (size_t)row * D_);
    float4 v = xr[t];
    float s  = v.x + v.y + v.z + v.w;
    float ss = v.x*v.x + v.y*v.y + v.z*v.z + v.w*v.w;
    #pragma unroll
    for (int o = 16; o > 0; o >>= 1) {
        s  += __shfl_xor_sync(0xffffffffu, s,  o);
        ss += __shfl_xor_sync(0xffffffffu, ss, o);
    }
    __shared__ float shs[8], shq[8];
    int w = t >> 5, l = t & 31;
    if (l == 0) { shs[w] = s; shq[w] = ss; }
    __syncthreads();
    float S = 0.f, Q = 0.f;
    #pragma unroll
    for (int i = 0; i < 8; i++) { S += shs[i]; Q += shq[i]; }
    float mean = S * (1.f / (float)D_);
    float var  = (Q - (float)D_ * mean * mean) * (1.f / (float)(D_ - 1));
    float inv  = rsqrtf(var + 1e-9f);
    const float4 g  = ((const float4*)gamma)[t];
    const float4 be = ((const float4*)beta)[t];
    float o0 = g.x * (v.x - mean) * inv + be.x;
    float o1 = g.y * (v.y - mean) * inv + be.y;
    float o2 = g.z * (v.z - mean) * inv + be.z;
    float o3 = g.w * (v.w - mean) * inv + be.w;
    size_t idx = (size_t)row * (D_/4) + t;
    ((uint2*)yh)[idx] = make_uint2(pk2h(o0, o1), pk2h(o2, o3));
}

// ---------------- LayerNorm (LN2) -> fp16 -----------------------------------
__global__ __launch_bounds__(256) void layernorm_kernel(
    const float* __restrict__ x, const float* __restrict__ gamma,
    const float* __restrict__ beta, h16* __restrict__ yh)
{
    int row = blockIdx.x;
    int t = threadIdx.x;
    const float4* xr = (const float4*)(x + (size_t)row * D_);
    float4 v = xr[t];
    float s  = v.x + v.y + v.z + v.w;
    float ss = v.x*v.x + v.y*v.y + v.z*v.z + v.w*v.w;
    #pragma unroll
    for (int o = 16; o > 0; o >>= 1) {
        s  += __shfl_xor_sync(0xffffffffu, s,  o);
        ss += __shfl_xor_sync(0xffffffffu, ss, o);
    }
    __shared__ float shs[8], shq[8];
    int w = t >> 5, l = t & 31;
    if (l == 0) { shs[w] = s; shq[w] = ss; }
    __syncthreads();
    float S = 0.f, Q = 0.f;
    #pragma unroll
    for (int i = 0; i < 8; i++) { S += shs[i]; Q += shq[i]; }
    float mean = S * (1.f / (float)D_);
    float var  = (Q - (float)D_ * mean * mean) * (1.f / (float)(D_ - 1));
    float inv  = rsqrtf(var + 1e-9f);
    const float4 g  = ((const float4*)gamma)[t];
    const float4 be = ((const float4*)beta)[t];
    float o0 = g.x * (v.x - mean) * inv + be.x;
    float o1 = g.y * (v.y - mean) * inv + be.y;
    float o2 = g.z * (v.z - mean) * inv + be.z;
    float o3 = g.w * (v.w - mean) * inv + be.w;
    size_t idx = (size_t)row * (D_/4) + t;
    ((uint2*)yh)[idx] = make_uint2(pk2h(o0, o1), pk2h(o2, o3));
}

// ---------------- mma.sync fp16 single-term GEMM (R11 form) -----------------
#define MATB 16384   // 128 rows x 128 bytes
#define STB  (2 * MATB)
#define SMEM_GEMM (3 * STB)   // 98304

template<bool RELU, bool BIAS, bool RES, bool OUTF16>
__global__ __launch_bounds__(256, 2) void tc_gemm(
    const h16* __restrict__ Ah, const h16* __restrict__ Bh,
    const float* __restrict__ bias, const float* __restrict__ res,
    float* __restrict__ Cf, h16* __restrict__ Ch,
    int M, int N, int K)
{
    extern __shared__ char smem[];
    uint32_t sb = smem_to_u32(smem);
    int tid = threadIdx.x;
    int lane = tid & 31, wid = tid >> 5;
    int wm = wid & 1, wn = wid >> 1;
    int row0 = blockIdx.y * 128, col0 = blockIdx.x * 128;

    int lm = tid >> 1;
    int lc = tid & 1;
    const h16* aHs = Ah + (size_t)(row0 + lm) * K + lc * 32;
    const h16* bHs = Bh + (size_t)(col0 + lm) * K + lc * 32;
    uint32_t dRow = (uint32_t)(lm << 7);
    uint32_t dCol[4];
    #pragma unroll
    for (int j = 0; j < 4; j++)
        dCol[j] = (uint32_t)(((lc * 64 + j * 16) ^ ((lm & 7) << 4)));

    auto load_stage = [&](int p, int kt) {
        uint32_t s0 = sb + p * STB + dRow;
        size_t ko = (size_t)kt * 64;
        #pragma unroll
        for (int j = 0; j < 4; j++) cp16(s0 + dCol[j], aHs + ko + j * 8);
        #pragma unroll
        for (int j = 0; j < 4; j++) cp16(s0 + MATB + dCol[j], bHs + ko + j * 8);
    };

    int g = lane >> 3, r = lane & 7;
    uint32_t aRow[4], bRow[2];
    #pragma unroll
    for (int mt = 0; mt < 4; mt++)
        aRow[mt] = (uint32_t)((wm * 64 + mt * 16 + (g & 1) * 8 + r) << 7);
    #pragma unroll
    for (int nb = 0; nb < 2; nb++)
        bRow[nb] = (uint32_t)((wn * 32 + nb * 16 + (g >> 1) * 8 + r) << 7);
    uint32_t aColSw[4], bColSw[4];
    #pragma unroll
    for (int h = 0; h < 4; h++) {
        aColSw[h] = (uint32_t)(((h << 5) + ((g >> 1) << 4)) ^ (r << 4));
        bColSw[h] = (uint32_t)(((h << 5) + ((g & 1) << 4)) ^ (r << 4));
    }

    float acc[4][4][4];
    #pragma unroll
    for (int i = 0; i < 4; i++)
        #pragma unroll
        for (int j = 0; j < 4; j++)
            #pragma unroll
            for (int e = 0; e < 4; e++) acc[i][j][e] = 0.f;

    int KT = K / 64;
    load_stage(0, 0); CP_COMMIT();
    load_stage(1, 1); CP_COMMIT();

    int s = 0;
    for (int kt = 0; kt < KT; kt++) {
        __syncthreads();
        if (kt + 2 < KT) {
            int sw = s + 2; if (sw >= 3) sw -= 3;
            load_stage(sw, kt + 2);
        }
        CP_COMMIT();
        asm volatile("cp.async.wait_group 2;" ::: "memory");
        uint32_t st = sb + s * STB;
        #pragma unroll
        for (int h = 0; h < 4; h++) {
            uint32_t ah[4][4], bh[2][4];
            #pragma unroll
            for (int mt = 0; mt < 4; mt++)
                ldm4(ah[mt], st + aRow[mt] + aColSw[h]);
            #pragma unroll
            for (int nb = 0; nb < 2; nb++)
                ldm4(bh[nb], st + MATB + bRow[nb] + bColSw[h]);
            #pragma unroll
            for (int mt = 0; mt < 4; mt++)
                #pragma unroll
                for (int nt = 0; nt < 4; nt++)
                    mma_f16(acc[mt][nt], ah[mt],
                            bh[nt >> 1][(nt & 1) * 2], bh[nt >> 1][(nt & 1) * 2 + 1]);
        }
        if (++s >= 3) s = 0;
    }

    // epilogue
    #pragma unroll
    for (int mt = 0; mt < 4; mt++) {
        int r_lo = row0 + wm * 64 + mt * 16 + (lane >> 2);
        #pragma unroll
        for (int nt = 0; nt < 4; nt++) {
            int col = col0 + wn * 32 + nt * 8 + (lane & 3) * 2;
            float* d = acc[mt][nt];
            float bi0 = 0.f, bi1 = 0.f;
            if (BIAS) { bi0 = __ldg(bias + col); bi1 = __ldg(bias + col + 1); }
            #pragma unroll
            for (int half = 0; half < 2; half++) {
                int row = r_lo + half * 8;
                float v0 = d[half * 2 + 0], v1 = d[half * 2 + 1];
                if (BIAS) { v0 += bi0; v1 += bi1; }
                if (RELU) { v0 = fmaxf(v0, 0.f); v1 = fmaxf(v1, 0.f); }
                size_t base = (size_t)row * N + col;
                if (RES) {
                    float2 rr = *(const float2*)(res + base);
                    v0 += rr.x; v1 += rr.y;
                }
                if (OUTF16) {
                    *(uint32_t*)(Ch + base) = pk2h(v0, v1);
                } else {
                    *(float2*)(Cf + base) = make_float2(v0, v1);
                }
            }
        }
    }
}

// ---------------- Tensor-core flash attention (scores pre-scaled) -----------
// 64-key chunks, 3-stage ring, 2 CTAs/SM, conditional accumulator rescale.
#define AROWB 144
#define A_V   9216
#define A_M   18432
#define A_STRIDE 18688
#define A_SMEM (3 * A_STRIDE)   // 56064

__global__ __launch_bounds__(256, 2) void attention_tc(
    const h16* __restrict__ qkvh, const int* __restrict__ mask,
    h16* __restrict__ oh)
{
    extern __shared__ char smem[];
    uint32_t sb = smem_to_u32(smem);
    int tid = threadIdx.x, lane = tid & 31, w = tid >> 5;
    int bh_ = blockIdx.y, b = bh_ >> 4, h = bh_ & 15;
    int q0 = blockIdx.x * 128;
    size_t hoff = (size_t)h * DKH;
    int g = lane >> 3, r = lane & 7;

    // ---- stage Q (hi only) into stage-0 region, read to regs, then reuse ---
    {
        int lm = tid >> 1;
        int lc = (tid & 1) * 4;
        size_t go = (size_t)(b * S_ + q0 + lm) * QKVS + hoff + lc * 8;
        uint32_t d0 = sb + (uint32_t)(lm * AROWB + lc * 16);
        #pragma unroll
        for (int j = 0; j < 4; j++)
            cp16(d0 + j * 16, qkvh + go + j * 8);
        CP_COMMIT();
    }
    asm volatile("cp.async.wait_group 0;" ::: "memory");
    __syncthreads();

    uint32_t Qh4[4][4];
    {
        uint32_t aoff = sb + (uint32_t)((w * 16 + (g & 1) * 8 + r) * AROWB + (g >> 1) * 16);
        #pragma unroll
        for (int ks = 0; ks < 4; ks++)
            ldm4(Qh4[ks], aoff + ks * 32);
    }
    __syncthreads();   // protect stage-0 region before K/V chunk 0 overwrites

    float m0 = -1e30f, m1 = -1e30f, l0 = 0.f, l1 = 0.f;
    float acc[8][4];
    #pragma unroll
    for (int i = 0; i < 8; i++)
        #pragma unroll
        for (int e = 0; e < 4; e++) acc[i][e] = 0.f;

    const h16* kbh = qkvh + (size_t)b * S_ * QKVS + D_ + hoff;
    const h16* vb  = qkvh + (size_t)b * S_ * QKVS + 2 * D_ + hoff;
    const int* mrow = mask + (size_t)b * S_;

    auto load_chunk = [&](int stg_i, int c) {
        uint32_t stg = sb + stg_i * A_STRIDE;
        int lm = tid >> 2;
        int lc = (tid & 3) * 2;
        size_t go = (size_t)(c * 64 + lm) * QKVS + lc * 8;
        uint32_t d = stg + (uint32_t)(lm * AROWB + lc * 16);
        cp16(d,            kbh + go);
        cp16(d + 16,       kbh + go + 8);
        cp16(d + A_V,      vb + go);
        cp16(d + A_V + 16, vb + go + 8);
        if (tid < 64)
            asm volatile("cp.async.ca.shared.global [%0], [%1], 4;"
                :: "r"(stg + A_M + tid * 4), "l"(mrow + c * 64 + tid));
    };

    const int NC = S_ / 64;   // 32
    load_chunk(0, 0); CP_COMMIT();
    load_chunk(1, 1); CP_COMMIT();

    uint32_t bKoff = (uint32_t)(((g >> 1) * 8 + r) * AROWB + (g & 1) * 16);
    uint32_t vOff  = (uint32_t)(((g & 1) * 8 + r) * AROWB + (g >> 1) * 16);

    int si = 0;
    for (int c = 0; c < NC; c++) {
        __syncthreads();                    // stage (c-1)%3 fully consumed
        if (c + 2 < NC) {
            int sw = si + 2; if (sw >= 3) sw -= 3;
            load_chunk(sw, c + 2);          // overlaps with compute below
        }
        CP_COMMIT();
        asm volatile("cp.async.wait_group 2;" ::: "memory");   // chunk c ready
        uint32_t stg = sb + si * A_STRIDE;

        float s[8][4];
        #pragma unroll
        for (int i = 0; i < 8; i++)
            #pragma unroll
            for (int e = 0; e < 4; e++) s[i][e] = 0.f;

        // S = Q K^T (single-term fp16; scores arrive pre-scaled by 1/8)
        #pragma unroll
        for (int ks = 0; ks < 4; ks++) {
            #pragma unroll
            for (int nb = 0; nb < 4; nb++) {
                uint32_t bh4[4];
                ldm4(bh4, stg + bKoff + nb * (16 * AROWB) + ks * 32);
                mma_f16(s[nb*2],   Qh4[ks], bh4[0], bh4[1]);
                mma_f16(s[nb*2+1], Qh4[ks], bh4[2], bh4[3]);
            }
        }

        // mask (scores already scaled)
        const int* ms = (const int*)(smem + (size_t)si * A_STRIDE + A_M);
        #pragma unroll
        for (int nt = 0; nt < 8; nt++) {
            int cc = nt * 8 + (lane & 3) * 2;
            int mv0 = ms[cc], mv1 = ms[cc + 1];
            if (mv0 == 0) { s[nt][0] = -1e9f; s[nt][2] = -1e9f; }
            if (mv1 == 0) { s[nt][1] = -1e9f; s[nt][3] = -1e9f; }
        }

        // online softmax (rows r and r+8 per thread)
        float mx0 = -1e30f, mx1 = -1e30f;
        #pragma unroll
        for (int nt = 0; nt < 8; nt++) {
            mx0 = fmaxf(mx0, fmaxf(s[nt][0], s[nt][1]));
            mx1 = fmaxf(mx1, fmaxf(s[nt][2], s[nt][3]));
        }
        mx0 = fmaxf(mx0, __shfl_xor_sync(0xffffffffu, mx0, 1));
        mx0 = fmaxf(mx0, __shfl_xor_sync(0xffffffffu, mx0, 2));
        mx1 = fmaxf(mx1, __shfl_xor_sync(0xffffffffu, mx1, 1));
        mx1 = fmaxf(mx1, __shfl_xor_sync(0xffffffffu, mx1, 2));
        float mn0 = fmaxf(m0, mx0), mn1 = fmaxf(m1, mx1);

        // conditional rescale: skip when no row in the warp updated its max
        // (then sc == exp(0) == 1 exactly -> acc/l unchanged, bit-identical)
        bool upd = (mn0 > m0) || (mn1 > m1);
        if (__any_sync(0xffffffffu, upd)) {
            float sc0 = __expf(m0 - mn0), sc1 = __expf(m1 - mn1);
            l0 *= sc0; l1 *= sc1;
            #pragma unroll
            for (int no = 0; no < 8; no++) {
                acc[no][0] *= sc0; acc[no][1] *= sc0;
                acc[no][2] *= sc1; acc[no][3] *= sc1;
            }
        }
        m0 = mn0; m1 = mn1;

        float rs0 = 0.f, rs1 = 0.f;
        #pragma unroll
        for (int nt = 0; nt < 8; nt++) {
            s[nt][0] = __expf(s[nt][0] - mn0); rs0 += s[nt][0];
            s[nt][1] = __expf(s[nt][1] - mn0); rs0 += s[nt][1];
            s[nt][2] = __expf(s[nt][2] - mn1); rs1 += s[nt][2];
            s[nt][3] = __expf(s[nt][3] - mn1); rs1 += s[nt][3];
        }
        rs0 += __shfl_xor_sync(0xffffffffu, rs0, 1);
        rs0 += __shfl_xor_sync(0xffffffffu, rs0, 2);
        rs1 += __shfl_xor_sync(0xffffffffu, rs1, 1);
        rs1 += __shfl_xor_sync(0xffffffffu, rs1, 2);
        l0 += rs0;
        l1 += rs1;

        // O += P V   (P fragments repacked directly as A operand)
        #pragma unroll
        for (int kb = 0; kb < 4; kb++) {
            uint32_t a4[4];
            a4[0] = pk2h(s[kb*2][0],   s[kb*2][1]);
            a4[1] = pk2h(s[kb*2][2],   s[kb*2][3]);
            a4[2] = pk2h(s[kb*2+1][0], s[kb*2+1][1]);
            a4[3] = pk2h(s[kb*2+1][2], s[kb*2+1][3]);
            #pragma unroll
            for (int db = 0; db < 4; db++) {
                uint32_t bv[4];
                ldm4t(bv, stg + A_V + vOff + kb * (16 * AROWB) + db * 32);
                mma_f16(acc[db*2],   a4, bv[0], bv[1]);
                mma_f16(acc[db*2+1], a4, bv[2], bv[3]);
            }
        }

        if (++si >= 3) si = 0;
    }

    // ---- output: O / l -> fp16 (hi only) ----
    float inv0 = 1.f / l0, inv1 = 1.f / l1;
    int row0 = q0 + w * 16 + (lane >> 2);
    size_t t0 = (size_t)(b * S_ + row0) * D_ + hoff;
    size_t t1 = t0 + (size_t)8 * D_;
    #pragma unroll
    for (int no = 0; no < 8; no++) {
        int cc = no * 8 + (lane & 3) * 2;
        *(uint32_t*)(oh + t0 + cc) = pk2h(acc[no][0] * inv0, acc[no][1] * inv0);
        *(uint32_t*)(oh + t1 + cc) = pk2h(acc[no][2] * inv1, acc[no][3] * inv1);
    }
}

// ---------------- launch ----------------------------------------------------
extern "C" void kernel_launch(void* const* d_in, const int* in_sizes, int n_in,
                              void* d_out, int out_size)
{
    (void)in_sizes; (void)n_in; (void)out_size;
    const float* x    = (const float*)d_in[0];
    const int*   mask = (const int*)  d_in[1];
    const float* wq   = (const float*)d_in[2];
    const float* wk   = (const float*)d_in[3];
    const float* wv   = (const float*)d_in[4];
    const float* wo   = (const float*)d_in[5];
    const float* w1   = (const float*)d_in[6];
    const float* b1   = (const float*)d_in[7];
    const float* w2   = (const float*)d_in[8];
    const float* b2   = (const float*)d_in[9];
    const float* g1   = (const float*)d_in[10];
    const float* be1  = (const float*)d_in[11];
    const float* g2   = (const float*)d_in[12];
    const float* be2  = (const float*)d_in[13];
    float* out = (float*)d_out;

    float *h1;
    h16 *zh, *qkvh, *ah, *mh;
    h16 *wc, *wop, *w1p, *w2p;
    cudaGetSymbolAddress((void**)&h1, g_h1);
    cudaGetSymbolAddress((void**)&zh, g_zh);
    cudaGetSymbolAddress((void**)&qkvh, g_qkvh);
    cudaGetSymbolAddress((void**)&ah, g_ah);
    cudaGetSymbolAddress((void**)&mh, g_mh);
    cudaGetSymbolAddress((void**)&wc, g_wc);
    cudaGetSymbolAddress((void**)&wop, g_wo);
    cudaGetSymbolAddress((void**)&w1p, g_w1);
    cudaGetSymbolAddress((void**)&w2p, g_w2);

    cudaFuncSetAttribute(tc_gemm<false,false,false,true >, cudaFuncAttributeMaxDynamicSharedMemorySize, SMEM_GEMM);
    cudaFuncSetAttribute(tc_gemm<false,false,true ,false>, cudaFuncAttributeMaxDynamicSharedMemorySize, SMEM_GEMM);
    cudaFuncSetAttribute(tc_gemm<true ,true ,false,true >, cudaFuncAttributeMaxDynamicSharedMemorySize, SMEM_GEMM);
    cudaFuncSetAttribute(tc_gemm<false,true ,true ,false>, cudaFuncAttributeMaxDynamicSharedMemorySize, SMEM_GEMM);
    cudaFuncSetAttribute(attention_tc, cudaFuncAttributeMaxDynamicSharedMemorySize, A_SMEM);

    // 1: fused prep — weight conversions + LN1 (one launch)
    prep_kernel<<<12288 + NT, 256>>>(wq, wk, wv, wo, w1, w2,
                                     wc, wop, w1p, w2p, x, g1, be1, zh);

    // 2: fused QKV GEMM (N = 3072) -> fp16
    dim3 gQKV(QKVS / 128, NT / 128);
    tc_gemm<false,false,false,true><<<gQKV, 256, SMEM_GEMM>>>(
        zh, wc, nullptr, nullptr, nullptr, qkvh, NT, QKVS, D_);

    // 3: attention (tensor core) -> fp16
    dim3 gAtt(S_ / 128, B_ * H_);
    attention_tc<<<gAtt, 256, A_SMEM>>>(qkvh, mask, ah);

    // 4: h1 = x + attn @ wo^T
    dim3 gP(D_ / 128, NT / 128);
    tc_gemm<false,false,true,false><<<gP, 256, SMEM_GEMM>>>(
        ah, wop, nullptr, x, h1, nullptr, NT, D_, D_);

    // 5: LN2 -> fp16
    layernorm_kernel<<<NT, 256>>>(h1, g2, be2, zh);

    // 6: FFN1: mid = relu(z @ w1^T + b1) -> fp16
    dim3 gF1(DFF_ / 128, NT / 128);
    tc_gemm<true,true,false,true><<<gF1, 256, SMEM_GEMM>>>(
        zh, w1p, b1, nullptr, nullptr, mh, NT, DFF_, D_);

    // 7: FFN2: out = h1 + mid @ w2^T + b2
    dim3 gF2(D_ / 128, NT / 128);
    tc_gemm<false,true,true,false><<<gF2, 256, SMEM_GEMM>>>(
        mh, w2p, b2, h1, out, nullptr, NT, D_, DFF_);
}